// round 6
// baseline (speedup 1.0000x reference)
#include <cuda_runtime.h>
#include <cuda_bf16.h>
#include <cstdint>

// Problem constants
#define EMBED   1024
#define NHEAD   16
#define HDIM    64
#define BATCH   4
#define SEQ     2048
#define MROWS   (BATCH * SEQ)                 // 8192
#define QKVN    (BATCH * NHEAD * SEQ * HDIM)  // 8388608

// ---------------------------------------------------------------------------
// Persistent scratch (bf16 hi/lo split everywhere)
// ---------------------------------------------------------------------------
__device__ __align__(16) __nv_bfloat16 g_xh [MROWS * EMBED];
__device__ __align__(16) __nv_bfloat16 g_xl [MROWS * EMBED];
__device__ __align__(16) __nv_bfloat16 g_wqh[3 * EMBED * EMBED];
__device__ __align__(16) __nv_bfloat16 g_wql[3 * EMBED * EMBED];
__device__ __align__(16) __nv_bfloat16 g_wph[EMBED * EMBED];
__device__ __align__(16) __nv_bfloat16 g_wpl[EMBED * EMBED];
__device__ __align__(16) __nv_bfloat16 g_qh [QKVN];   // [B,H,T,D]
__device__ __align__(16) __nv_bfloat16 g_ql [QKVN];
__device__ __align__(16) __nv_bfloat16 g_kh [QKVN];   // [B,H,T,D]
__device__ __align__(16) __nv_bfloat16 g_kl [QKVN];
__device__ __align__(16) __nv_bfloat16 g_vth[QKVN];   // [B,H,D,T]  (transposed)
__device__ __align__(16) __nv_bfloat16 g_vtl[QKVN];
__device__ __align__(16) __nv_bfloat16 g_aoh[MROWS * EMBED];   // [B*T, C]
__device__ __align__(16) __nv_bfloat16 g_aol[MROWS * EMBED];

// ---------------------------------------------------------------------------
// helpers
// ---------------------------------------------------------------------------
__device__ __forceinline__ void mma_bf16(float* c, const uint32_t* a, const uint32_t* b) {
    asm volatile(
        "mma.sync.aligned.m16n8k16.row.col.f32.bf16.bf16.f32 "
        "{%0,%1,%2,%3}, {%4,%5,%6,%7}, {%8,%9}, {%0,%1,%2,%3};"
        : "+f"(c[0]), "+f"(c[1]), "+f"(c[2]), "+f"(c[3])
        : "r"(a[0]), "r"(a[1]), "r"(a[2]), "r"(a[3]), "r"(b[0]), "r"(b[1]));
}
__device__ __forceinline__ void splitpack(float x0, float x1, uint32_t& hp, uint32_t& lp) {
    __nv_bfloat16 h0 = __float2bfloat16_rn(x0);
    __nv_bfloat16 h1 = __float2bfloat16_rn(x1);
    __nv_bfloat16 l0 = __float2bfloat16_rn(x0 - __bfloat162float(h0));
    __nv_bfloat16 l1 = __float2bfloat16_rn(x1 - __bfloat162float(h1));
    hp = (uint32_t)__bfloat16_as_ushort(h0) | ((uint32_t)__bfloat16_as_ushort(h1) << 16);
    lp = (uint32_t)__bfloat16_as_ushort(l0) | ((uint32_t)__bfloat16_as_ushort(l1) << 16);
}
__device__ __forceinline__ void cpasync16(void* s, const void* g) {
    uint32_t sa = (uint32_t)__cvta_generic_to_shared(s);
    asm volatile("cp.async.cg.shared.global [%0], [%1], 16;\n" :: "r"(sa), "l"(g));
}
#define CP_COMMIT() asm volatile("cp.async.commit_group;\n" ::: "memory")
#define CP_WAIT1()  asm volatile("cp.async.wait_group 1;\n"  ::: "memory")
#define CP_WAIT0()  asm volatile("cp.async.wait_group 0;\n"  ::: "memory")

// ---------------------------------------------------------------------------
// prep: split fp32 -> bf16 hi/lo (vectorized, 4 elems/thread)
// ---------------------------------------------------------------------------
__global__ void split_f32(const float4* __restrict__ src,
                          uint2* __restrict__ hi,
                          uint2* __restrict__ lo, int n4)
{
    int i = blockIdx.x * blockDim.x + threadIdx.x;
    if (i < n4) {
        float4 v = src[i];
        uint32_t h0, l0, h1, l1;
        splitpack(v.x, v.y, h0, l0);
        splitpack(v.z, v.w, h1, l1);
        hi[i] = make_uint2(h0, h1);
        lo[i] = make_uint2(l0, l1);
    }
}

// ---------------------------------------------------------------------------
// split-2 bf16 GEMM:  C = A @ B^T.  A:[M,K] rm hi/lo, B:[N,K] rm hi/lo.
// Block 128x128, kTile 32 (bf16), 256 threads (8 warps, warp tile 32x64).
// 2-stage cp.async pipeline (80KB smem -> 2 CTAs/SM).
// Pass-major MMA ordering (hh, hl, lh) to break accumulator RAW chains.
// MODE 0: fp32 store C.  MODE 1: QKV split/scatter epilogue.
// ---------------------------------------------------------------------------
#define GST    20                          // smem row stride in u32 (16 data + 4 pad)
#define GCOMP  (128 * GST)                 // u32 per component per stage
#define GSTAGE (4 * GCOMP)                 // Ah, Al, Bh, Bl
#define GEMM_SMEM (2 * GSTAGE * 4)         // 81920 bytes

template <int MODE>
__global__ void __launch_bounds__(256, 2)
gemm_bf2(const __nv_bfloat16* __restrict__ Ah, const __nv_bfloat16* __restrict__ Al,
         const __nv_bfloat16* __restrict__ Bh, const __nv_bfloat16* __restrict__ Bl,
         float* __restrict__ C, int K, int N)
{
    extern __shared__ uint32_t smu[];

    const int tid  = threadIdx.x;
    const int lane = tid & 31;
    const int w    = tid >> 5;
    const int gr   = lane >> 2;
    const int tig  = lane & 3;
    const int wm   = w & 3;              // 32-row quadrant
    const int wn   = w >> 2;             // 64-col half

    const int row0 = blockIdx.y * 128;
    const int col0 = blockIdx.x * 128;

    float acc[2][8][4];
#pragma unroll
    for (int i = 0; i < 2; i++)
#pragma unroll
        for (int j = 0; j < 8; j++)
#pragma unroll
            for (int e = 0; e < 4; e++) acc[i][j][e] = 0.f;

    // stage loader: per component 128 rows x 32 bf16 (4 x 16B chunks per row)
    auto loadTile = [&](int s, int kt) {
        uint32_t* st = smu + (size_t)s * GSTAGE;
#pragma unroll
        for (int p = 0; p < 2; p++) {
            int c   = tid + 256 * p;         // 0..511
            int row = c >> 2;
            int ch  = c & 3;
            uint32_t* d0 = st + row * GST + ch * 4;
            size_t ga = (size_t)(row0 + row) * K + kt + ch * 8;
            size_t gb = (size_t)(col0 + row) * K + kt + ch * 8;
            cpasync16(d0,                 Ah + ga);
            cpasync16(d0 + GCOMP,         Al + ga);
            cpasync16(d0 + 2 * GCOMP,     Bh + gb);
            cpasync16(d0 + 3 * GCOMP,     Bl + gb);
        }
    };

    const int nk = K / 32;
    loadTile(0, 0);  CP_COMMIT();
    loadTile(1, 32); CP_COMMIT();

    for (int t = 0; t < nk; t++) {
        const int s = t & 1;
        if (t >= nk - 2) { CP_WAIT0(); } else { CP_WAIT1(); }
        __syncthreads();

        const uint32_t* ash = smu + (size_t)s * GSTAGE;
        const uint32_t* asl = ash + GCOMP;
        const uint32_t* bsh = ash + 2 * GCOMP;
        const uint32_t* bsl = ash + 3 * GCOMP;

#pragma unroll
        for (int ks = 0; ks < 2; ks++) {
            const int base = ks * 8;
            uint32_t ah[2][4], al_[2][4];
#pragma unroll
            for (int mt = 0; mt < 2; mt++) {
                int r = wm * 32 + mt * 16 + gr;
                ah[mt][0]  = ash[(r    ) * GST + base + tig];
                ah[mt][1]  = ash[(r + 8) * GST + base + tig];
                ah[mt][2]  = ash[(r    ) * GST + base + tig + 4];
                ah[mt][3]  = ash[(r + 8) * GST + base + tig + 4];
                al_[mt][0] = asl[(r    ) * GST + base + tig];
                al_[mt][1] = asl[(r + 8) * GST + base + tig];
                al_[mt][2] = asl[(r    ) * GST + base + tig + 4];
                al_[mt][3] = asl[(r + 8) * GST + base + tig + 4];
            }
            uint32_t bh[8][2], bl[8][2];
#pragma unroll
            for (int nt = 0; nt < 8; nt++) {
                int cn = wn * 64 + nt * 8 + gr;
                bh[nt][0] = bsh[cn * GST + base + tig];
                bh[nt][1] = bsh[cn * GST + base + tig + 4];
                bl[nt][0] = bsl[cn * GST + base + tig];
                bl[nt][1] = bsl[cn * GST + base + tig + 4];
            }
            // pass-major ordering: 16 independent accumulators between reuses
#pragma unroll
            for (int mt = 0; mt < 2; mt++)
#pragma unroll
                for (int nt = 0; nt < 8; nt++)
                    mma_bf16(acc[mt][nt], ah[mt], bh[nt]);
#pragma unroll
            for (int mt = 0; mt < 2; mt++)
#pragma unroll
                for (int nt = 0; nt < 8; nt++)
                    mma_bf16(acc[mt][nt], ah[mt], bl[nt]);
#pragma unroll
            for (int mt = 0; mt < 2; mt++)
#pragma unroll
                for (int nt = 0; nt < 8; nt++)
                    mma_bf16(acc[mt][nt], al_[mt], bh[nt]);
        }
        __syncthreads();
        if (t + 2 < nk) { loadTile(s, (t + 2) * 32); CP_COMMIT(); }
    }

    // ---- epilogue
#pragma unroll
    for (int mt = 0; mt < 2; mt++) {
#pragma unroll
        for (int e2 = 0; e2 < 2; e2++) {
            int r = row0 + wm * 32 + mt * 16 + gr + e2 * 8;
#pragma unroll
            for (int nt = 0; nt < 8; nt++) {
                int n = col0 + wn * 64 + nt * 8 + 2 * tig;
                float v0 = acc[mt][nt][e2 * 2 + 0];
                float v1 = acc[mt][nt][e2 * 2 + 1];
                if (MODE == 0) {
                    *(float2*)&C[(size_t)r * N + n] = make_float2(v0, v1);
                } else {
                    int b   = r >> 11;            // / SEQ
                    int tk  = r & (SEQ - 1);
                    int sec = n >> 10;
                    int c   = n & 1023;
                    int h   = c >> 6;
                    int d   = c & 63;
                    int bh_ = b * NHEAD + h;
                    if (sec == 2) {
                        // V: store transposed [B,H,D,T], scalar bf16
                        size_t i0 = ((size_t)bh_ * HDIM + d) * SEQ + tk;
                        __nv_bfloat16 h0 = __float2bfloat16_rn(v0);
                        __nv_bfloat16 h1 = __float2bfloat16_rn(v1);
                        g_vth[i0]       = h0;
                        g_vth[i0 + SEQ] = h1;
                        g_vtl[i0]       = __float2bfloat16_rn(v0 - __bfloat162float(h0));
                        g_vtl[i0 + SEQ] = __float2bfloat16_rn(v1 - __bfloat162float(h1));
                    } else {
                        uint32_t hp, lp;
                        splitpack(v0, v1, hp, lp);
                        size_t i2 = (((size_t)bh_ * SEQ + tk) * HDIM + d) >> 1;  // u32 idx
                        if (sec == 0) {
                            ((uint32_t*)g_qh)[i2] = hp;
                            ((uint32_t*)g_ql)[i2] = lp;
                        } else {
                            ((uint32_t*)g_kh)[i2] = hp;
                            ((uint32_t*)g_kl)[i2] = lp;
                        }
                    }
                }
            }
        }
    }
}

// ---------------------------------------------------------------------------
// Causal flash attention, split-2 bf16 mma.sync. Br=128, Bc=64, D=64.
// 256 threads = 8 warps; warp w owns q rows [16w, 16w+16).
// 2-stage cp.async prefetch of K/V (hi/lo). Q pre-scaled by 0.125 in bf16.
// Pass-major MMA ordering in both S and PV loops.
// grid: (SEQ/128, B*H)
// ---------------------------------------------------------------------------
#define AST 36                                   // smem row stride in u32
#define ATT_QP_U32  (2 * 128 * AST)              // QPh + QPl
#define ATT_STG_U32 (4 * 64 * AST)               // Ksh, Ksl, Vth, Vtl per stage
#define ATT_SMEM ((ATT_QP_U32 + 2 * ATT_STG_U32) * 4)   // 110592 bytes

__global__ void __launch_bounds__(256, 2)
attn_bf2()
{
    extern __shared__ uint32_t smu[];
    uint32_t* QPh = smu;                    // [128][AST]  Q hi, reused for P hi
    uint32_t* QPl = QPh + 128 * AST;        // [128][AST]  Q lo, reused for P lo
    uint32_t* Stg = QPl + 128 * AST;        // 2 stages of K/V hi/lo

    const int tid  = threadIdx.x;
    const int lane = tid & 31;
    const int w    = tid >> 5;
    const int gr   = lane >> 2;
    const int tig  = lane & 3;
    const int m0   = w * 16;

    const int qb = blockIdx.x;
    const int bh = blockIdx.y;
    const int b  = bh >> 4;
    const int h  = bh & 15;
    const int q0 = qb * 128;

    const size_t bhoff = (size_t)bh * SEQ * HDIM;
    const size_t vtoff = (size_t)bh * HDIM * SEQ;

    // K/V prefetch (cp.async, 2 stages)
    auto loadKV = [&](int s, int kt) {
        const int k0 = kt * 64;
        uint32_t* st = Stg + s * ATT_STG_U32;
        for (int i = tid; i < 64 * 8; i += 256) {
            int row = i >> 3, ch = i & 7;
            uint32_t* d = st + row * AST + ch * 4;
            size_t gk = bhoff + (size_t)(k0 + row) * HDIM + ch * 8;
            size_t gv = vtoff + (size_t)row * SEQ + k0 + ch * 8;
            cpasync16(d,                g_kh  + gk);
            cpasync16(d +     64 * AST, g_kl  + gk);
            cpasync16(d + 2 * 64 * AST, g_vth + gv);
            cpasync16(d + 3 * 64 * AST, g_vtl + gv);
        }
    };

    const int ktmax = 2 * qb + 1;          // >= 1 always
    loadKV(0, 0); CP_COMMIT();
    loadKV(1, 1); CP_COMMIT();

    // ---- load Q tile (hi/lo) into smem, pre-scaled by 0.125 (exact in bf16)
    {
        const __nv_bfloat162 c2 = __floats2bfloat162_rn(0.125f, 0.125f);
        const uint4* qh4 = (const uint4*)(g_qh + bhoff + (size_t)q0 * HDIM);
        const uint4* ql4 = (const uint4*)(g_ql + bhoff + (size_t)q0 * HDIM);
        for (int i = tid; i < 128 * 8; i += 256) {
            int row = i >> 3, ch = i & 7;
            uint4 a = qh4[row * 8 + ch];
            __nv_bfloat162* ap = (__nv_bfloat162*)&a;
#pragma unroll
            for (int e = 0; e < 4; e++) ap[e] = __hmul2(ap[e], c2);
            *(uint4*)&QPh[row * AST + ch * 4] = a;
            uint4 bq = ql4[row * 8 + ch];
            __nv_bfloat162* bp = (__nv_bfloat162*)&bq;
#pragma unroll
            for (int e = 0; e < 4; e++) bp[e] = __hmul2(bp[e], c2);
            *(uint4*)&QPl[row * AST + ch * 4] = bq;
        }
    }
    __syncthreads();

    // ---- build persistent Q fragments
    uint32_t qfh[4][4], qfl[4][4];
#pragma unroll
    for (int dk = 0; dk < 4; dk++) {
        qfh[dk][0] = QPh[(m0 + gr    ) * AST + dk * 8 + tig];
        qfh[dk][1] = QPh[(m0 + gr + 8) * AST + dk * 8 + tig];
        qfh[dk][2] = QPh[(m0 + gr    ) * AST + dk * 8 + tig + 4];
        qfh[dk][3] = QPh[(m0 + gr + 8) * AST + dk * 8 + tig + 4];
        qfl[dk][0] = QPl[(m0 + gr    ) * AST + dk * 8 + tig];
        qfl[dk][1] = QPl[(m0 + gr + 8) * AST + dk * 8 + tig];
        qfl[dk][2] = QPl[(m0 + gr    ) * AST + dk * 8 + tig + 4];
        qfl[dk][3] = QPl[(m0 + gr + 8) * AST + dk * 8 + tig + 4];
    }
    __syncthreads();   // QP now free for P

    float o[8][4];
#pragma unroll
    for (int nt = 0; nt < 8; nt++)
#pragma unroll
        for (int e = 0; e < 4; e++) o[nt][e] = 0.f;
    float mrow[2] = {-1e30f, -1e30f};
    float lrow[2] = {0.f, 0.f};

    for (int kt = 0; kt <= ktmax; kt++) {
        const int s = kt & 1;
        if (kt == ktmax) { CP_WAIT0(); } else { CP_WAIT1(); }
        __syncthreads();

        const uint32_t* Ksh = Stg + s * ATT_STG_U32;
        const uint32_t* Ksl = Ksh + 64 * AST;
        const uint32_t* Vth = Ksh + 2 * 64 * AST;
        const uint32_t* Vtl = Ksh + 3 * 64 * AST;
        const int k0 = kt * 64;

        // ---- S = Q K^T (split-2, pass-major over nt)
        float sfr[8][4];
#pragma unroll
        for (int nt = 0; nt < 8; nt++)
#pragma unroll
            for (int e = 0; e < 4; e++) sfr[nt][e] = 0.f;

#pragma unroll
        for (int dk = 0; dk < 4; dk++) {
            uint32_t kfh[8][2], kfl[8][2];
#pragma unroll
            for (int nt = 0; nt < 8; nt++) {
                int kn = nt * 8 + gr;
                kfh[nt][0] = Ksh[kn * AST + dk * 8 + tig];
                kfh[nt][1] = Ksh[kn * AST + dk * 8 + tig + 4];
                kfl[nt][0] = Ksl[kn * AST + dk * 8 + tig];
                kfl[nt][1] = Ksl[kn * AST + dk * 8 + tig + 4];
            }
#pragma unroll
            for (int nt = 0; nt < 8; nt++)
                mma_bf16(sfr[nt], qfh[dk], kfh[nt]);
#pragma unroll
            for (int nt = 0; nt < 8; nt++)
                mma_bf16(sfr[nt], qfh[dk], kfl[nt]);
#pragma unroll
            for (int nt = 0; nt < 8; nt++)
                mma_bf16(sfr[nt], qfl[dk], kfh[nt]);
        }

        // ---- causal mask (only near the diagonal)
        if (k0 + 63 > q0 + m0) {
#pragma unroll
            for (int nt = 0; nt < 8; nt++)
#pragma unroll
                for (int e = 0; e < 4; e++) {
                    int rg = q0 + m0 + gr + (e >> 1) * 8;
                    int cg = k0 + nt * 8 + 2 * tig + (e & 1);
                    if (cg > rg) sfr[nt][e] = -1e30f;
                }
        }

        // ---- online softmax (thread rows: gr, gr+8)
        float mx0 = -1e30f, mx1 = -1e30f;
#pragma unroll
        for (int nt = 0; nt < 8; nt++) {
            mx0 = fmaxf(mx0, fmaxf(sfr[nt][0], sfr[nt][1]));
            mx1 = fmaxf(mx1, fmaxf(sfr[nt][2], sfr[nt][3]));
        }
        mx0 = fmaxf(mx0, __shfl_xor_sync(0xffffffffu, mx0, 1));
        mx0 = fmaxf(mx0, __shfl_xor_sync(0xffffffffu, mx0, 2));
        mx1 = fmaxf(mx1, __shfl_xor_sync(0xffffffffu, mx1, 1));
        mx1 = fmaxf(mx1, __shfl_xor_sync(0xffffffffu, mx1, 2));

        float nm0 = fmaxf(mrow[0], mx0);
        float nm1 = fmaxf(mrow[1], mx1);
        float f0  = __expf(mrow[0] - nm0);
        float f1  = __expf(mrow[1] - nm1);

        float ps0 = 0.f, ps1 = 0.f;
#pragma unroll
        for (int nt = 0; nt < 8; nt++) {
            float p0 = __expf(sfr[nt][0] - nm0);
            float p1 = __expf(sfr[nt][1] - nm0);
            float p2 = __expf(sfr[nt][2] - nm1);
            float p3 = __expf(sfr[nt][3] - nm1);
            ps0 += p0 + p1;
            ps1 += p2 + p3;
            uint32_t hp, lp;
            splitpack(p0, p1, hp, lp);
            QPh[(m0 + gr) * AST + nt * 4 + tig] = hp;
            QPl[(m0 + gr) * AST + nt * 4 + tig] = lp;
            splitpack(p2, p3, hp, lp);
            QPh[(m0 + gr + 8) * AST + nt * 4 + tig] = hp;
            QPl[(m0 + gr + 8) * AST + nt * 4 + tig] = lp;
        }
        ps0 += __shfl_xor_sync(0xffffffffu, ps0, 1);
        ps0 += __shfl_xor_sync(0xffffffffu, ps0, 2);
        ps1 += __shfl_xor_sync(0xffffffffu, ps1, 1);
        ps1 += __shfl_xor_sync(0xffffffffu, ps1, 2);

        lrow[0] = lrow[0] * f0 + ps0;
        lrow[1] = lrow[1] * f1 + ps1;
        mrow[0] = nm0;
        mrow[1] = nm1;
#pragma unroll
        for (int nt = 0; nt < 8; nt++) {
            o[nt][0] *= f0; o[nt][1] *= f0;
            o[nt][2] *= f1; o[nt][3] *= f1;
        }
        __syncwarp();    // P is per-warp rows only

        // ---- O += P V (split-2, pass-major over nt)
#pragma unroll
        for (int kk = 0; kk < 4; kk++) {
            uint32_t pfh[4], pfl[4];
            pfh[0] = QPh[(m0 + gr    ) * AST + kk * 8 + tig];
            pfh[1] = QPh[(m0 + gr + 8) * AST + kk * 8 + tig];
            pfh[2] = QPh[(m0 + gr    ) * AST + kk * 8 + tig + 4];
            pfh[3] = QPh[(m0 + gr + 8) * AST + kk * 8 + tig + 4];
            pfl[0] = QPl[(m0 + gr    ) * AST + kk * 8 + tig];
            pfl[1] = QPl[(m0 + gr + 8) * AST + kk * 8 + tig];
            pfl[2] = QPl[(m0 + gr    ) * AST + kk * 8 + tig + 4];
            pfl[3] = QPl[(m0 + gr + 8) * AST + kk * 8 + tig + 4];
            uint32_t vfh[8][2], vfl[8][2];
#pragma unroll
            for (int nt = 0; nt < 8; nt++) {
                int dn = nt * 8 + gr;
                vfh[nt][0] = Vth[dn * AST + kk * 8 + tig];
                vfh[nt][1] = Vth[dn * AST + kk * 8 + tig + 4];
                vfl[nt][0] = Vtl[dn * AST + kk * 8 + tig];
                vfl[nt][1] = Vtl[dn * AST + kk * 8 + tig + 4];
            }
#pragma unroll
            for (int nt = 0; nt < 8; nt++)
                mma_bf16(o[nt], pfh, vfh[nt]);
#pragma unroll
            for (int nt = 0; nt < 8; nt++)
                mma_bf16(o[nt], pfh, vfl[nt]);
#pragma unroll
            for (int nt = 0; nt < 8; nt++)
                mma_bf16(o[nt], pfl, vfh[nt]);
        }
        __syncthreads();     // all warps done with stage s
        if (kt + 2 <= ktmax) { loadKV(s, kt + 2); CP_COMMIT(); }
    }

    // ---- normalize, split, store to g_ao (bf16 hi/lo, [B*T, C])
    float inv0 = 1.0f / lrow[0];
    float inv1 = 1.0f / lrow[1];
    int r0 = q0 + m0 + gr;
    uint32_t* aoh = (uint32_t*)g_aoh;
    uint32_t* aol = (uint32_t*)g_aol;
#pragma unroll
    for (int nt = 0; nt < 8; nt++) {
        size_t cu = (size_t)h * 32 + nt * 4 + tig;   // u32 col
        uint32_t hp, lp;
        splitpack(o[nt][0] * inv0, o[nt][1] * inv0, hp, lp);
        aoh[(size_t)(b * SEQ + r0) * (EMBED / 2) + cu] = hp;
        aol[(size_t)(b * SEQ + r0) * (EMBED / 2) + cu] = lp;
        splitpack(o[nt][2] * inv1, o[nt][3] * inv1, hp, lp);
        aoh[(size_t)(b * SEQ + r0 + 8) * (EMBED / 2) + cu] = hp;
        aol[(size_t)(b * SEQ + r0 + 8) * (EMBED / 2) + cu] = lp;
    }
}

// ---------------------------------------------------------------------------
extern "C" void kernel_launch(void* const* d_in, const int* in_sizes, int n_in,
                              void* d_out, int out_size)
{
    const float* x      = (const float*)d_in[0];   // [4,2048,1024]
    const float* W_qkv  = (const float*)d_in[1];   // [3072,1024]
    const float* W_proj = (const float*)d_in[2];   // [1024,1024]
    float* out = (float*)d_out;                    // [4,2048,1024]

    __nv_bfloat16 *xh, *xl, *wqh, *wql, *wph, *wpl, *aoh, *aol;
    cudaGetSymbolAddress((void**)&xh,  g_xh);
    cudaGetSymbolAddress((void**)&xl,  g_xl);
    cudaGetSymbolAddress((void**)&wqh, g_wqh);
    cudaGetSymbolAddress((void**)&wql, g_wql);
    cudaGetSymbolAddress((void**)&wph, g_wph);
    cudaGetSymbolAddress((void**)&wpl, g_wpl);
    cudaGetSymbolAddress((void**)&aoh, g_aoh);
    cudaGetSymbolAddress((void**)&aol, g_aol);

    // 0) split inputs into bf16 hi/lo (vectorized by 4)
    {
        int n1 = MROWS * EMBED / 4, n2 = 3 * EMBED * EMBED / 4, n3 = EMBED * EMBED / 4;
        split_f32<<<(n1 + 255) / 256, 256>>>((const float4*)x, (uint2*)xh, (uint2*)xl, n1);
        split_f32<<<(n2 + 255) / 256, 256>>>((const float4*)W_qkv, (uint2*)wqh, (uint2*)wql, n2);
        split_f32<<<(n3 + 255) / 256, 256>>>((const float4*)W_proj, (uint2*)wph, (uint2*)wpl, n3);
    }

    // 1) QKV projection with split/scatter epilogue
    {
        cudaFuncSetAttribute((const void*)gemm_bf2<1>,
                             cudaFuncAttributeMaxDynamicSharedMemorySize, GEMM_SMEM);
        dim3 grid(3 * EMBED / 128, MROWS / 128);
        gemm_bf2<1><<<grid, 256, GEMM_SMEM>>>(xh, xl, wqh, wql, nullptr, EMBED, 3 * EMBED);
    }

    // 2) causal flash attention -> g_ao (split bf16)
    {
        cudaFuncSetAttribute((const void*)attn_bf2,
                             cudaFuncAttributeMaxDynamicSharedMemorySize, ATT_SMEM);
        dim3 grid(SEQ / 128, BATCH * NHEAD);
        attn_bf2<<<grid, 256, ATT_SMEM>>>();
    }

    // 3) output projection -> d_out (fp32)
    {
        cudaFuncSetAttribute((const void*)gemm_bf2<0>,
                             cudaFuncAttributeMaxDynamicSharedMemorySize, GEMM_SMEM);
        dim3 grid(EMBED / 128, MROWS / 128);
        gemm_bf2<0><<<grid, 256, GEMM_SMEM>>>(aoh, aol, wph, wpl, out, EMBED, EMBED);
    }
}

// round 7
// speedup vs baseline: 1.4140x; 1.4140x over previous
#include <cuda_runtime.h>
#include <cuda_fp16.h>
#include <cstdint>

// Problem constants
#define EMBED   1024
#define NHEAD   16
#define HDIM    64
#define BATCH   4
#define SEQ     2048
#define MROWS   (BATCH * SEQ)                 // 8192
#define QKVN    (BATCH * NHEAD * SEQ * HDIM)  // 8388608

// ---------------------------------------------------------------------------
// Persistent scratch (fp16; activations split hi/lo, weights/K/V single fp16)
// ---------------------------------------------------------------------------
__device__ __align__(16) __half g_xh [MROWS * EMBED];
__device__ __align__(16) __half g_xl [MROWS * EMBED];
__device__ __align__(16) __half g_wq [3 * EMBED * EMBED];
__device__ __align__(16) __half g_wp [EMBED * EMBED];
__device__ __align__(16) __half g_qh [QKVN];   // [B,H,T,D] split
__device__ __align__(16) __half g_ql [QKVN];
__device__ __align__(16) __half g_k  [QKVN];   // [B,H,T,D] single
__device__ __align__(16) __half g_vt [QKVN];   // [B,H,D,T] single (transposed)
__device__ __align__(16) __half g_aoh[MROWS * EMBED];   // [B*T, C] split
__device__ __align__(16) __half g_aol[MROWS * EMBED];

// ---------------------------------------------------------------------------
// helpers
// ---------------------------------------------------------------------------
__device__ __forceinline__ void mma_f16(float* c, const uint32_t* a, const uint32_t* b) {
    asm volatile(
        "mma.sync.aligned.m16n8k16.row.col.f32.f16.f16.f32 "
        "{%0,%1,%2,%3}, {%4,%5,%6,%7}, {%8,%9}, {%0,%1,%2,%3};"
        : "+f"(c[0]), "+f"(c[1]), "+f"(c[2]), "+f"(c[3])
        : "r"(a[0]), "r"(a[1]), "r"(a[2]), "r"(a[3]), "r"(b[0]), "r"(b[1]));
}
__device__ __forceinline__ uint32_t packh(float x0, float x1) {
    __half2 h = __floats2half2_rn(x0, x1);
    return *(uint32_t*)&h;
}
__device__ __forceinline__ void splitpackh(float x0, float x1, uint32_t& hp, uint32_t& lp) {
    __half h0 = __float2half_rn(x0);
    __half h1 = __float2half_rn(x1);
    __half l0 = __float2half_rn(x0 - __half2float(h0));
    __half l1 = __float2half_rn(x1 - __half2float(h1));
    hp = (uint32_t)__half_as_ushort(h0) | ((uint32_t)__half_as_ushort(h1) << 16);
    lp = (uint32_t)__half_as_ushort(l0) | ((uint32_t)__half_as_ushort(l1) << 16);
}
__device__ __forceinline__ void cpasync16(void* s, const void* g) {
    uint32_t sa = (uint32_t)__cvta_generic_to_shared(s);
    asm volatile("cp.async.cg.shared.global [%0], [%1], 16;\n" :: "r"(sa), "l"(g));
}
#define CP_COMMIT() asm volatile("cp.async.commit_group;\n" ::: "memory")
#define CP_WAIT1()  asm volatile("cp.async.wait_group 1;\n"  ::: "memory")
#define CP_WAIT0()  asm volatile("cp.async.wait_group 0;\n"  ::: "memory")

// ---------------------------------------------------------------------------
// prep kernels
// ---------------------------------------------------------------------------
__global__ void split_f32h(const float4* __restrict__ src,
                           uint2* __restrict__ hi,
                           uint2* __restrict__ lo, int n4)
{
    int i = blockIdx.x * blockDim.x + threadIdx.x;
    if (i < n4) {
        float4 v = src[i];
        uint32_t h0, l0, h1, l1;
        splitpackh(v.x, v.y, h0, l0);
        splitpackh(v.z, v.w, h1, l1);
        hi[i] = make_uint2(h0, h1);
        lo[i] = make_uint2(l0, l1);
    }
}
__global__ void cvt_f32h(const float4* __restrict__ src,
                         uint2* __restrict__ dst, int n4)
{
    int i = blockIdx.x * blockDim.x + threadIdx.x;
    if (i < n4) {
        float4 v = src[i];
        dst[i] = make_uint2(packh(v.x, v.y), packh(v.z, v.w));
    }
}

// ---------------------------------------------------------------------------
// 2-pass fp16 GEMM:  C = A @ B^T.  A:[M,K] rm hi/lo (exact), B:[N,K] rm fp16.
// Block 128x128, kTile 32 (fp16), 256 threads (8 warps, warp tile 32x64).
// 2-stage cp.async pipeline. MMAs: Ah*B + Al*B.
// MODE 0: fp32 store C.  MODE 1: QKV scatter epilogue.
// ---------------------------------------------------------------------------
#define GST    20                          // smem row stride in u32 (16 data + 4 pad)
#define GCOMP  (128 * GST)                 // u32 per component per stage
#define GSTAGE (3 * GCOMP)                 // Ah, Al, B
#define GEMM_SMEM (2 * GSTAGE * 4)         // 61440 bytes

template <int MODE>
__global__ void __launch_bounds__(256, 2)
gemm_h2(const __half* __restrict__ Ah, const __half* __restrict__ Al,
        const __half* __restrict__ B,
        float* __restrict__ C, int K, int N)
{
    extern __shared__ uint32_t smu[];

    const int tid  = threadIdx.x;
    const int lane = tid & 31;
    const int w    = tid >> 5;
    const int gr   = lane >> 2;
    const int tig  = lane & 3;
    const int wm   = w & 3;              // 32-row quadrant
    const int wn   = w >> 2;             // 64-col half

    const int row0 = blockIdx.y * 128;
    const int col0 = blockIdx.x * 128;

    float acc[2][8][4];
#pragma unroll
    for (int i = 0; i < 2; i++)
#pragma unroll
        for (int j = 0; j < 8; j++)
#pragma unroll
            for (int e = 0; e < 4; e++) acc[i][j][e] = 0.f;

    // stage loader: per component 128 rows x 32 fp16 (4 x 16B chunks per row)
    auto loadTile = [&](int s, int kt) {
        uint32_t* st = smu + (size_t)s * GSTAGE;
#pragma unroll
        for (int p = 0; p < 2; p++) {
            int c   = tid + 256 * p;         // 0..511
            int row = c >> 2;
            int ch  = c & 3;
            uint32_t* d0 = st + row * GST + ch * 4;
            size_t ga = (size_t)(row0 + row) * K + kt + ch * 8;
            size_t gb = (size_t)(col0 + row) * K + kt + ch * 8;
            cpasync16(d0,             Ah + ga);
            cpasync16(d0 + GCOMP,     Al + ga);
            cpasync16(d0 + 2 * GCOMP, B + gb);
        }
    };

    const int nk = K / 32;
    loadTile(0, 0);  CP_COMMIT();
    loadTile(1, 32); CP_COMMIT();

    for (int t = 0; t < nk; t++) {
        const int s = t & 1;
        if (t >= nk - 2) { CP_WAIT0(); } else { CP_WAIT1(); }
        __syncthreads();

        const uint32_t* ash = smu + (size_t)s * GSTAGE;
        const uint32_t* asl = ash + GCOMP;
        const uint32_t* bs  = ash + 2 * GCOMP;

#pragma unroll
        for (int ks = 0; ks < 2; ks++) {
            const int base = ks * 8;
            uint32_t ah[2][4], al_[2][4];
#pragma unroll
            for (int mt = 0; mt < 2; mt++) {
                int r = wm * 32 + mt * 16 + gr;
                ah[mt][0]  = ash[(r    ) * GST + base + tig];
                ah[mt][1]  = ash[(r + 8) * GST + base + tig];
                ah[mt][2]  = ash[(r    ) * GST + base + tig + 4];
                ah[mt][3]  = ash[(r + 8) * GST + base + tig + 4];
                al_[mt][0] = asl[(r    ) * GST + base + tig];
                al_[mt][1] = asl[(r + 8) * GST + base + tig];
                al_[mt][2] = asl[(r    ) * GST + base + tig + 4];
                al_[mt][3] = asl[(r + 8) * GST + base + tig + 4];
            }
            uint32_t bf[8][2];
#pragma unroll
            for (int nt = 0; nt < 8; nt++) {
                int cn = wn * 64 + nt * 8 + gr;
                bf[nt][0] = bs[cn * GST + base + tig];
                bf[nt][1] = bs[cn * GST + base + tig + 4];
            }
#pragma unroll
            for (int mt = 0; mt < 2; mt++)
#pragma unroll
                for (int nt = 0; nt < 8; nt++)
                    mma_f16(acc[mt][nt], ah[mt], bf[nt]);
#pragma unroll
            for (int mt = 0; mt < 2; mt++)
#pragma unroll
                for (int nt = 0; nt < 8; nt++)
                    mma_f16(acc[mt][nt], al_[mt], bf[nt]);
        }
        __syncthreads();
        if (t + 2 < nk) { loadTile(s, (t + 2) * 32); CP_COMMIT(); }
    }

    // ---- epilogue
#pragma unroll
    for (int mt = 0; mt < 2; mt++) {
#pragma unroll
        for (int e2 = 0; e2 < 2; e2++) {
            int r = row0 + wm * 32 + mt * 16 + gr + e2 * 8;
#pragma unroll
            for (int nt = 0; nt < 8; nt++) {
                int n = col0 + wn * 64 + nt * 8 + 2 * tig;
                float v0 = acc[mt][nt][e2 * 2 + 0];
                float v1 = acc[mt][nt][e2 * 2 + 1];
                if (MODE == 0) {
                    *(float2*)&C[(size_t)r * N + n] = make_float2(v0, v1);
                } else {
                    int b   = r >> 11;            // / SEQ
                    int tk  = r & (SEQ - 1);
                    int sec = n >> 10;
                    int c   = n & 1023;
                    int h   = c >> 6;
                    int d   = c & 63;
                    int bh_ = b * NHEAD + h;
                    if (sec == 0) {
                        // Q: split hi/lo (exact operand for S)
                        uint32_t hp, lp;
                        splitpackh(v0, v1, hp, lp);
                        size_t i2 = (((size_t)bh_ * SEQ + tk) * HDIM + d) >> 1;
                        ((uint32_t*)g_qh)[i2] = hp;
                        ((uint32_t*)g_ql)[i2] = lp;
                    } else if (sec == 1) {
                        // K: single fp16
                        size_t i2 = (((size_t)bh_ * SEQ + tk) * HDIM + d) >> 1;
                        ((uint32_t*)g_k)[i2] = packh(v0, v1);
                    } else {
                        // V: single fp16, transposed [B,H,D,T]
                        size_t i0 = ((size_t)bh_ * HDIM + d) * SEQ + tk;
                        g_vt[i0]       = __float2half_rn(v0);
                        g_vt[i0 + SEQ] = __float2half_rn(v1);
                    }
                }
            }
        }
    }
}

// ---------------------------------------------------------------------------
// Causal flash attention, 2-pass fp16 mma.sync. Br=128, Bc=64, D=64.
// 256 threads = 8 warps; warp w owns q rows [16w, 16w+16).
// Q split hi/lo (pre-scaled by 0.125, exact); K, V single fp16.
// P split hi/lo on the fly. 2-stage cp.async K/V prefetch.
// grid: (SEQ/128, B*H)
// ---------------------------------------------------------------------------
#define AST 36                                   // smem row stride in u32
#define ATT_QP_U32  (2 * 128 * AST)              // QPh + QPl
#define ATT_STG_U32 (2 * 64 * AST)               // Ks, Vt per stage
#define ATT_SMEM ((ATT_QP_U32 + 2 * ATT_STG_U32) * 4)   // 73728 bytes

__global__ void __launch_bounds__(256, 2)
attn_h2()
{
    extern __shared__ uint32_t smu[];
    uint32_t* QPh = smu;                    // [128][AST]  Q hi, reused for P hi
    uint32_t* QPl = QPh + 128 * AST;        // [128][AST]  Q lo, reused for P lo
    uint32_t* Stg = QPl + 128 * AST;        // 2 stages of {Ks, Vt}

    const int tid  = threadIdx.x;
    const int lane = tid & 31;
    const int w    = tid >> 5;
    const int gr   = lane >> 2;
    const int tig  = lane & 3;
    const int m0   = w * 16;

    const int qb = blockIdx.x;
    const int bh = blockIdx.y;
    const int b  = bh >> 4;
    const int h  = bh & 15;
    const int q0 = qb * 128;

    const size_t bhoff = (size_t)bh * SEQ * HDIM;
    const size_t vtoff = (size_t)bh * HDIM * SEQ;

    // K/V prefetch (cp.async, 2 stages)
    auto loadKV = [&](int s, int kt) {
        const int k0 = kt * 64;
        uint32_t* st = Stg + s * ATT_STG_U32;
        for (int i = tid; i < 64 * 8; i += 256) {
            int row = i >> 3, ch = i & 7;
            uint32_t* d = st + row * AST + ch * 4;
            size_t gk = bhoff + (size_t)(k0 + row) * HDIM + ch * 8;
            size_t gv = vtoff + (size_t)row * SEQ + k0 + ch * 8;
            cpasync16(d,            g_k  + gk);
            cpasync16(d + 64 * AST, g_vt + gv);
        }
    };

    const int ktmax = 2 * qb + 1;          // >= 1 always
    loadKV(0, 0); CP_COMMIT();
    loadKV(1, 1); CP_COMMIT();

    // ---- load Q tile (hi/lo) into smem, pre-scaled by 0.125 (exact in fp16)
    {
        const __half2 c2 = __floats2half2_rn(0.125f, 0.125f);
        const uint4* qh4 = (const uint4*)(g_qh + bhoff + (size_t)q0 * HDIM);
        const uint4* ql4 = (const uint4*)(g_ql + bhoff + (size_t)q0 * HDIM);
        for (int i = tid; i < 128 * 8; i += 256) {
            int row = i >> 3, ch = i & 7;
            uint4 a = qh4[row * 8 + ch];
            __half2* ap = (__half2*)&a;
#pragma unroll
            for (int e = 0; e < 4; e++) ap[e] = __hmul2(ap[e], c2);
            *(uint4*)&QPh[row * AST + ch * 4] = a;
            uint4 bq = ql4[row * 8 + ch];
            __half2* bp = (__half2*)&bq;
#pragma unroll
            for (int e = 0; e < 4; e++) bp[e] = __hmul2(bp[e], c2);
            *(uint4*)&QPl[row * AST + ch * 4] = bq;
        }
    }
    __syncthreads();

    // ---- build persistent Q fragments
    uint32_t qfh[4][4], qfl[4][4];
#pragma unroll
    for (int dk = 0; dk < 4; dk++) {
        qfh[dk][0] = QPh[(m0 + gr    ) * AST + dk * 8 + tig];
        qfh[dk][1] = QPh[(m0 + gr + 8) * AST + dk * 8 + tig];
        qfh[dk][2] = QPh[(m0 + gr    ) * AST + dk * 8 + tig + 4];
        qfh[dk][3] = QPh[(m0 + gr + 8) * AST + dk * 8 + tig + 4];
        qfl[dk][0] = QPl[(m0 + gr    ) * AST + dk * 8 + tig];
        qfl[dk][1] = QPl[(m0 + gr + 8) * AST + dk * 8 + tig];
        qfl[dk][2] = QPl[(m0 + gr    ) * AST + dk * 8 + tig + 4];
        qfl[dk][3] = QPl[(m0 + gr + 8) * AST + dk * 8 + tig + 4];
    }
    __syncthreads();   // QP now free for P

    float o[8][4];
#pragma unroll
    for (int nt = 0; nt < 8; nt++)
#pragma unroll
        for (int e = 0; e < 4; e++) o[nt][e] = 0.f;
    float mrow[2] = {-1e30f, -1e30f};
    float lrow[2] = {0.f, 0.f};

    for (int kt = 0; kt <= ktmax; kt++) {
        const int s = kt & 1;
        if (kt == ktmax) { CP_WAIT0(); } else { CP_WAIT1(); }
        __syncthreads();

        const uint32_t* Ks = Stg + s * ATT_STG_U32;
        const uint32_t* Vt = Ks + 64 * AST;
        const int k0 = kt * 64;

        // ---- S = Q K^T (2-pass)
        float sfr[8][4];
#pragma unroll
        for (int nt = 0; nt < 8; nt++)
#pragma unroll
            for (int e = 0; e < 4; e++) sfr[nt][e] = 0.f;

#pragma unroll
        for (int dk = 0; dk < 4; dk++) {
            uint32_t kf[8][2];
#pragma unroll
            for (int nt = 0; nt < 8; nt++) {
                int kn = nt * 8 + gr;
                kf[nt][0] = Ks[kn * AST + dk * 8 + tig];
                kf[nt][1] = Ks[kn * AST + dk * 8 + tig + 4];
            }
#pragma unroll
            for (int nt = 0; nt < 8; nt++)
                mma_f16(sfr[nt], qfh[dk], kf[nt]);
#pragma unroll
            for (int nt = 0; nt < 8; nt++)
                mma_f16(sfr[nt], qfl[dk], kf[nt]);
        }

        // ---- causal mask (only near the diagonal)
        if (k0 + 63 > q0 + m0) {
#pragma unroll
            for (int nt = 0; nt < 8; nt++)
#pragma unroll
                for (int e = 0; e < 4; e++) {
                    int rg = q0 + m0 + gr + (e >> 1) * 8;
                    int cg = k0 + nt * 8 + 2 * tig + (e & 1);
                    if (cg > rg) sfr[nt][e] = -1e30f;
                }
        }

        // ---- online softmax (thread rows: gr, gr+8)
        float mx0 = -1e30f, mx1 = -1e30f;
#pragma unroll
        for (int nt = 0; nt < 8; nt++) {
            mx0 = fmaxf(mx0, fmaxf(sfr[nt][0], sfr[nt][1]));
            mx1 = fmaxf(mx1, fmaxf(sfr[nt][2], sfr[nt][3]));
        }
        mx0 = fmaxf(mx0, __shfl_xor_sync(0xffffffffu, mx0, 1));
        mx0 = fmaxf(mx0, __shfl_xor_sync(0xffffffffu, mx0, 2));
        mx1 = fmaxf(mx1, __shfl_xor_sync(0xffffffffu, mx1, 1));
        mx1 = fmaxf(mx1, __shfl_xor_sync(0xffffffffu, mx1, 2));

        float nm0 = fmaxf(mrow[0], mx0);
        float nm1 = fmaxf(mrow[1], mx1);
        float f0  = __expf(mrow[0] - nm0);
        float f1  = __expf(mrow[1] - nm1);

        float ps0 = 0.f, ps1 = 0.f;
#pragma unroll
        for (int nt = 0; nt < 8; nt++) {
            float p0 = __expf(sfr[nt][0] - nm0);
            float p1 = __expf(sfr[nt][1] - nm0);
            float p2 = __expf(sfr[nt][2] - nm1);
            float p3 = __expf(sfr[nt][3] - nm1);
            ps0 += p0 + p1;
            ps1 += p2 + p3;
            uint32_t hp, lp;
            splitpackh(p0, p1, hp, lp);
            QPh[(m0 + gr) * AST + nt * 4 + tig] = hp;
            QPl[(m0 + gr) * AST + nt * 4 + tig] = lp;
            splitpackh(p2, p3, hp, lp);
            QPh[(m0 + gr + 8) * AST + nt * 4 + tig] = hp;
            QPl[(m0 + gr + 8) * AST + nt * 4 + tig] = lp;
        }
        ps0 += __shfl_xor_sync(0xffffffffu, ps0, 1);
        ps0 += __shfl_xor_sync(0xffffffffu, ps0, 2);
        ps1 += __shfl_xor_sync(0xffffffffu, ps1, 1);
        ps1 += __shfl_xor_sync(0xffffffffu, ps1, 2);

        lrow[0] = lrow[0] * f0 + ps0;
        lrow[1] = lrow[1] * f1 + ps1;
        mrow[0] = nm0;
        mrow[1] = nm1;
#pragma unroll
        for (int nt = 0; nt < 8; nt++) {
            o[nt][0] *= f0; o[nt][1] *= f0;
            o[nt][2] *= f1; o[nt][3] *= f1;
        }
        __syncwarp();    // P is per-warp rows only

        // ---- O += P V (2-pass)
#pragma unroll
        for (int kk = 0; kk < 4; kk++) {
            uint32_t pfh[4], pfl[4];
            pfh[0] = QPh[(m0 + gr    ) * AST + kk * 8 + tig];
            pfh[1] = QPh[(m0 + gr + 8) * AST + kk * 8 + tig];
            pfh[2] = QPh[(m0 + gr    ) * AST + kk * 8 + tig + 4];
            pfh[3] = QPh[(m0 + gr + 8) * AST + kk * 8 + tig + 4];
            pfl[0] = QPl[(m0 + gr    ) * AST + kk * 8 + tig];
            pfl[1] = QPl[(m0 + gr + 8) * AST + kk * 8 + tig];
            pfl[2] = QPl[(m0 + gr    ) * AST + kk * 8 + tig + 4];
            pfl[3] = QPl[(m0 + gr + 8) * AST + kk * 8 + tig + 4];
            uint32_t vf[8][2];
#pragma unroll
            for (int nt = 0; nt < 8; nt++) {
                int dn = nt * 8 + gr;
                vf[nt][0] = Vt[dn * AST + kk * 8 + tig];
                vf[nt][1] = Vt[dn * AST + kk * 8 + tig + 4];
            }
#pragma unroll
            for (int nt = 0; nt < 8; nt++)
                mma_f16(o[nt], pfh, vf[nt]);
#pragma unroll
            for (int nt = 0; nt < 8; nt++)
                mma_f16(o[nt], pfl, vf[nt]);
        }
        __syncthreads();     // all warps done with stage s
        if (kt + 2 <= ktmax) { loadKV(s, kt + 2); CP_COMMIT(); }
    }

    // ---- normalize, split, store to g_ao (fp16 hi/lo, [B*T, C])
    float inv0 = 1.0f / lrow[0];
    float inv1 = 1.0f / lrow[1];
    int r0 = q0 + m0 + gr;
    uint32_t* aoh = (uint32_t*)g_aoh;
    uint32_t* aol = (uint32_t*)g_aol;
#pragma unroll
    for (int nt = 0; nt < 8; nt++) {
        size_t cu = (size_t)h * 32 + nt * 4 + tig;   // u32 col
        uint32_t hp, lp;
        splitpackh(o[nt][0] * inv0, o[nt][1] * inv0, hp, lp);
        aoh[(size_t)(b * SEQ + r0) * (EMBED / 2) + cu] = hp;
        aol[(size_t)(b * SEQ + r0) * (EMBED / 2) + cu] = lp;
        splitpackh(o[nt][2] * inv1, o[nt][3] * inv1, hp, lp);
        aoh[(size_t)(b * SEQ + r0 + 8) * (EMBED / 2) + cu] = hp;
        aol[(size_t)(b * SEQ + r0 + 8) * (EMBED / 2) + cu] = lp;
    }
}

// ---------------------------------------------------------------------------
extern "C" void kernel_launch(void* const* d_in, const int* in_sizes, int n_in,
                              void* d_out, int out_size)
{
    const float* x      = (const float*)d_in[0];   // [4,2048,1024]
    const float* W_qkv  = (const float*)d_in[1];   // [3072,1024]
    const float* W_proj = (const float*)d_in[2];   // [1024,1024]
    float* out = (float*)d_out;                    // [4,2048,1024]

    __half *xh, *xl, *wq, *wp, *aoh, *aol;
    cudaGetSymbolAddress((void**)&xh,  g_xh);
    cudaGetSymbolAddress((void**)&xl,  g_xl);
    cudaGetSymbolAddress((void**)&wq,  g_wq);
    cudaGetSymbolAddress((void**)&wp,  g_wp);
    cudaGetSymbolAddress((void**)&aoh, g_aoh);
    cudaGetSymbolAddress((void**)&aol, g_aol);

    // 0) prep: x split hi/lo; weights single fp16
    {
        int n1 = MROWS * EMBED / 4, n2 = 3 * EMBED * EMBED / 4, n3 = EMBED * EMBED / 4;
        split_f32h<<<(n1 + 255) / 256, 256>>>((const float4*)x, (uint2*)xh, (uint2*)xl, n1);
        cvt_f32h<<<(n2 + 255) / 256, 256>>>((const float4*)W_qkv, (uint2*)wq, n2);
        cvt_f32h<<<(n3 + 255) / 256, 256>>>((const float4*)W_proj, (uint2*)wp, n3);
    }

    // 1) QKV projection with scatter epilogue
    {
        cudaFuncSetAttribute((const void*)gemm_h2<1>,
                             cudaFuncAttributeMaxDynamicSharedMemorySize, GEMM_SMEM);
        dim3 grid(3 * EMBED / 128, MROWS / 128);
        gemm_h2<1><<<grid, 256, GEMM_SMEM>>>(xh, xl, wq, nullptr, EMBED, 3 * EMBED);
    }

    // 2) causal flash attention -> g_ao (split fp16)
    {
        cudaFuncSetAttribute((const void*)attn_h2,
                             cudaFuncAttributeMaxDynamicSharedMemorySize, ATT_SMEM);
        dim3 grid(SEQ / 128, BATCH * NHEAD);
        attn_h2<<<grid, 256, ATT_SMEM>>>();
    }

    // 3) output projection -> d_out (fp32)
    {
        cudaFuncSetAttribute((const void*)gemm_h2<0>,
                             cudaFuncAttributeMaxDynamicSharedMemorySize, GEMM_SMEM);
        dim3 grid(EMBED / 128, MROWS / 128);
        gemm_h2<0><<<grid, 256, GEMM_SMEM>>>(aoh, aol, wp, out, EMBED, EMBED);
    }
}

// round 10
// speedup vs baseline: 1.4740x; 1.0424x over previous
#include <cuda_runtime.h>
#include <cuda_fp16.h>
#include <cstdint>

// Problem constants
#define EMBED   1024
#define NHEAD   16
#define HDIM    64
#define BATCH   4
#define SEQ     2048
#define MROWS   (BATCH * SEQ)                 // 8192
#define QKVN    (BATCH * NHEAD * SEQ * HDIM)  // 8388608

// ---------------------------------------------------------------------------
// Persistent scratch (fp16; activations split hi/lo, weights/K/V single fp16)
// ---------------------------------------------------------------------------
__device__ __align__(16) __half g_xh [MROWS * EMBED];
__device__ __align__(16) __half g_xl [MROWS * EMBED];
__device__ __align__(16) __half g_wq [3 * EMBED * EMBED];
__device__ __align__(16) __half g_wp [EMBED * EMBED];
__device__ __align__(16) __half g_qh [QKVN];   // [B,H,T,D] split
__device__ __align__(16) __half g_ql [QKVN];
__device__ __align__(16) __half g_k  [QKVN];   // [B,H,T,D] single
__device__ __align__(16) __half g_vt [QKVN];   // [B,H,D,T] single (transposed)
__device__ __align__(16) __half g_aoh[MROWS * EMBED];   // [B*T, C] split
__device__ __align__(16) __half g_aol[MROWS * EMBED];

// ---------------------------------------------------------------------------
// helpers
// ---------------------------------------------------------------------------
__device__ __forceinline__ void mma_f16(float* c, const uint32_t* a, const uint32_t* b) {
    asm volatile(
        "mma.sync.aligned.m16n8k16.row.col.f32.f16.f16.f32 "
        "{%0,%1,%2,%3}, {%4,%5,%6,%7}, {%8,%9}, {%0,%1,%2,%3};"
        : "+f"(c[0]), "+f"(c[1]), "+f"(c[2]), "+f"(c[3])
        : "r"(a[0]), "r"(a[1]), "r"(a[2]), "r"(a[3]), "r"(b[0]), "r"(b[1]));
}
__device__ __forceinline__ uint32_t packh(float x0, float x1) {
    __half2 h = __floats2half2_rn(x0, x1);
    return *(uint32_t*)&h;
}
__device__ __forceinline__ void splitpackh(float x0, float x1, uint32_t& hp, uint32_t& lp) {
    __half h0 = __float2half_rn(x0);
    __half h1 = __float2half_rn(x1);
    __half l0 = __float2half_rn(x0 - __half2float(h0));
    __half l1 = __float2half_rn(x1 - __half2float(h1));
    hp = (uint32_t)__half_as_ushort(h0) | ((uint32_t)__half_as_ushort(h1) << 16);
    lp = (uint32_t)__half_as_ushort(l0) | ((uint32_t)__half_as_ushort(l1) << 16);
}
__device__ __forceinline__ void cpasync16(void* s, const void* g) {
    uint32_t sa = (uint32_t)__cvta_generic_to_shared(s);
    asm volatile("cp.async.cg.shared.global [%0], [%1], 16;\n" :: "r"(sa), "l"(g));
}
#define CP_COMMIT() asm volatile("cp.async.commit_group;\n" ::: "memory")
#define CP_WAIT1()  asm volatile("cp.async.wait_group 1;\n"  ::: "memory")
#define CP_WAIT0()  asm volatile("cp.async.wait_group 0;\n"  ::: "memory")

// ---------------------------------------------------------------------------
// prep kernels
// ---------------------------------------------------------------------------
__global__ void split_f32h(const float4* __restrict__ src,
                           uint2* __restrict__ hi,
                           uint2* __restrict__ lo, int n4)
{
    int i = blockIdx.x * blockDim.x + threadIdx.x;
    if (i < n4) {
        float4 v = src[i];
        uint32_t h0, l0, h1, l1;
        splitpackh(v.x, v.y, h0, l0);
        splitpackh(v.z, v.w, h1, l1);
        hi[i] = make_uint2(h0, h1);
        lo[i] = make_uint2(l0, l1);
    }
}
__global__ void cvt_f32h(const float4* __restrict__ src,
                         uint2* __restrict__ dst, int n4)
{
    int i = blockIdx.x * blockDim.x + threadIdx.x;
    if (i < n4) {
        float4 v = src[i];
        dst[i] = make_uint2(packh(v.x, v.y), packh(v.z, v.w));
    }
}

// ---------------------------------------------------------------------------
// 2-pass fp16 GEMM:  C = A @ B^T.  A:[M,K] rm hi/lo (exact), B:[N,K] rm fp16.
// Block 128x128, kTile 32 (fp16), 256 threads (8 warps, warp tile 32x64).
// 2-stage cp.async pipeline. MMAs: Ah*B + Al*B.
// MODE 0: fp32 store C.  MODE 1: QKV scatter epilogue.
// ---------------------------------------------------------------------------
#define GST    20                          // smem row stride in u32 (16 data + 4 pad)
#define GCOMP  (128 * GST)                 // u32 per component per stage
#define GSTAGE (3 * GCOMP)                 // Ah, Al, B
#define GEMM_SMEM (2 * GSTAGE * 4)         // 61440 bytes

template <int MODE>
__global__ void __launch_bounds__(256, 2)
gemm_h2(const __half* __restrict__ Ah, const __half* __restrict__ Al,
        const __half* __restrict__ B,
        float* __restrict__ C, int K, int N)
{
    extern __shared__ uint32_t smu[];

    const int tid  = threadIdx.x;
    const int lane = tid & 31;
    const int w    = tid >> 5;
    const int gr   = lane >> 2;
    const int tig  = lane & 3;
    const int wm   = w & 3;              // 32-row quadrant
    const int wn   = w >> 2;             // 64-col half

    const int row0 = blockIdx.y * 128;
    const int col0 = blockIdx.x * 128;

    float acc[2][8][4];
#pragma unroll
    for (int i = 0; i < 2; i++)
#pragma unroll
        for (int j = 0; j < 8; j++)
#pragma unroll
            for (int e = 0; e < 4; e++) acc[i][j][e] = 0.f;

    // stage loader: per component 128 rows x 32 fp16 (4 x 16B chunks per row)
    auto loadTile = [&](int s, int kt) {
        uint32_t* st = smu + (size_t)s * GSTAGE;
#pragma unroll
        for (int p = 0; p < 2; p++) {
            int c   = tid + 256 * p;         // 0..511
            int row = c >> 2;
            int ch  = c & 3;
            uint32_t* d0 = st + row * GST + ch * 4;
            size_t ga = (size_t)(row0 + row) * K + kt + ch * 8;
            size_t gb = (size_t)(col0 + row) * K + kt + ch * 8;
            cpasync16(d0,             Ah + ga);
            cpasync16(d0 + GCOMP,     Al + ga);
            cpasync16(d0 + 2 * GCOMP, B + gb);
        }
    };

    const int nk = K / 32;
    loadTile(0, 0);  CP_COMMIT();
    loadTile(1, 32); CP_COMMIT();

    for (int t = 0; t < nk; t++) {
        const int s = t & 1;
        if (t >= nk - 2) { CP_WAIT0(); } else { CP_WAIT1(); }
        __syncthreads();

        const uint32_t* ash = smu + (size_t)s * GSTAGE;
        const uint32_t* asl = ash + GCOMP;
        const uint32_t* bs  = ash + 2 * GCOMP;

#pragma unroll
        for (int ks = 0; ks < 2; ks++) {
            const int base = ks * 8;
            uint32_t ah[2][4], al_[2][4];
#pragma unroll
            for (int mt = 0; mt < 2; mt++) {
                int r = wm * 32 + mt * 16 + gr;
                ah[mt][0]  = ash[(r    ) * GST + base + tig];
                ah[mt][1]  = ash[(r + 8) * GST + base + tig];
                ah[mt][2]  = ash[(r    ) * GST + base + tig + 4];
                ah[mt][3]  = ash[(r + 8) * GST + base + tig + 4];
                al_[mt][0] = asl[(r    ) * GST + base + tig];
                al_[mt][1] = asl[(r + 8) * GST + base + tig];
                al_[mt][2] = asl[(r    ) * GST + base + tig + 4];
                al_[mt][3] = asl[(r + 8) * GST + base + tig + 4];
            }
            uint32_t bf[8][2];
#pragma unroll
            for (int nt = 0; nt < 8; nt++) {
                int cn = wn * 64 + nt * 8 + gr;
                bf[nt][0] = bs[cn * GST + base + tig];
                bf[nt][1] = bs[cn * GST + base + tig + 4];
            }
#pragma unroll
            for (int mt = 0; mt < 2; mt++)
#pragma unroll
                for (int nt = 0; nt < 8; nt++)
                    mma_f16(acc[mt][nt], ah[mt], bf[nt]);
#pragma unroll
            for (int mt = 0; mt < 2; mt++)
#pragma unroll
                for (int nt = 0; nt < 8; nt++)
                    mma_f16(acc[mt][nt], al_[mt], bf[nt]);
        }
        __syncthreads();
        if (t + 2 < nk) { loadTile(s, (t + 2) * 32); CP_COMMIT(); }
    }

    // ---- epilogue
#pragma unroll
    for (int mt = 0; mt < 2; mt++) {
#pragma unroll
        for (int e2 = 0; e2 < 2; e2++) {
            int r = row0 + wm * 32 + mt * 16 + gr + e2 * 8;
#pragma unroll
            for (int nt = 0; nt < 8; nt++) {
                int n = col0 + wn * 64 + nt * 8 + 2 * tig;
                float v0 = acc[mt][nt][e2 * 2 + 0];
                float v1 = acc[mt][nt][e2 * 2 + 1];
                if (MODE == 0) {
                    *(float2*)&C[(size_t)r * N + n] = make_float2(v0, v1);
                } else {
                    int b   = r >> 11;            // / SEQ
                    int tk  = r & (SEQ - 1);
                    int sec = n >> 10;
                    int c   = n & 1023;
                    int h   = c >> 6;
                    int d   = c & 63;
                    int bh_ = b * NHEAD + h;
                    if (sec == 0) {
                        // Q: split hi/lo (exact operand for S)
                        uint32_t hp, lp;
                        splitpackh(v0, v1, hp, lp);
                        size_t i2 = (((size_t)bh_ * SEQ + tk) * HDIM + d) >> 1;
                        ((uint32_t*)g_qh)[i2] = hp;
                        ((uint32_t*)g_ql)[i2] = lp;
                    } else if (sec == 1) {
                        // K: single fp16
                        size_t i2 = (((size_t)bh_ * SEQ + tk) * HDIM + d) >> 1;
                        ((uint32_t*)g_k)[i2] = packh(v0, v1);
                    } else {
                        // V: single fp16, transposed [B,H,D,T]
                        size_t i0 = ((size_t)bh_ * HDIM + d) * SEQ + tk;
                        g_vt[i0]       = __float2half_rn(v0);
                        g_vt[i0 + SEQ] = __float2half_rn(v1);
                    }
                }
            }
        }
    }
}

// ---------------------------------------------------------------------------
// Causal flash attention, 2-pass fp16 mma.sync. Br=128, Bc=64, D=64.
// 256 threads = 8 warps; warp w owns q rows [16w, 16w+16).
// Q fragments loaded straight from gmem (L2-resident), pre-scaled by 0.125.
// P built register-direct from the S fragments (no smem round-trip).
// 2-stage cp.async K/V prefetch. Heavy q-blocks scheduled first (LPT).
// grid: (SEQ/128, B*H)
// ---------------------------------------------------------------------------
#define AST 36                                   // smem row stride in u32
#define ATT_STG_U32 (2 * 64 * AST)               // Ks, Vt per stage
#define ATT_SMEM (2 * ATT_STG_U32 * 4)           // 36864 bytes

__global__ void __launch_bounds__(256, 2)
attn_h2()
{
    extern __shared__ uint32_t smu[];
    uint32_t* Stg = smu;                    // 2 stages of {Ks, Vt}

    const int tid  = threadIdx.x;
    const int lane = tid & 31;
    const int w    = tid >> 5;
    const int gr   = lane >> 2;
    const int tig  = lane & 3;
    const int m0   = w * 16;

    const int qb = gridDim.x - 1 - blockIdx.x;   // longest-processing-time first
    const int bh = blockIdx.y;
    const int b  = bh >> 4;
    const int h  = bh & 15;
    const int q0 = qb * 128;

    const size_t bhoff = (size_t)bh * SEQ * HDIM;
    const size_t vtoff = (size_t)bh * HDIM * SEQ;

    // K/V prefetch (cp.async, 2 stages)
    auto loadKV = [&](int s, int kt) {
        const int k0 = kt * 64;
        uint32_t* st = Stg + s * ATT_STG_U32;
        for (int i = tid; i < 64 * 8; i += 256) {
            int row = i >> 3, ch = i & 7;
            uint32_t* d = st + row * AST + ch * 4;
            size_t gk = bhoff + (size_t)(k0 + row) * HDIM + ch * 8;
            size_t gv = vtoff + (size_t)row * SEQ + k0 + ch * 8;
            cpasync16(d,            g_k  + gk);
            cpasync16(d + 64 * AST, g_vt + gv);
        }
    };

    const int ktmax = 2 * qb + 1;          // >= 1 always
    loadKV(0, 0); CP_COMMIT();
    loadKV(1, 1); CP_COMMIT();

    // ---- Q fragments straight from gmem, pre-scaled by 0.125 (exact in fp16)
    uint32_t qfh[4][4], qfl[4][4];
    {
        const __half2 c2 = __floats2half2_rn(0.125f, 0.125f);
        const uint32_t* qhg = (const uint32_t*)(g_qh + bhoff + (size_t)q0 * HDIM);
        const uint32_t* qlg = (const uint32_t*)(g_ql + bhoff + (size_t)q0 * HDIM);
        const int r0i = (m0 + gr) * 32;          // u32 row stride = HDIM/2
        const int r1i = (m0 + gr + 8) * 32;
#pragma unroll
        for (int dk = 0; dk < 4; dk++) {
            uint32_t t0 = qhg[r0i + dk * 8 + tig];
            uint32_t t1 = qhg[r1i + dk * 8 + tig];
            uint32_t t2 = qhg[r0i + dk * 8 + tig + 4];
            uint32_t t3 = qhg[r1i + dk * 8 + tig + 4];
            __half2 s0 = __hmul2(*(__half2*)&t0, c2);
            __half2 s1 = __hmul2(*(__half2*)&t1, c2);
            __half2 s2 = __hmul2(*(__half2*)&t2, c2);
            __half2 s3 = __hmul2(*(__half2*)&t3, c2);
            qfh[dk][0] = *(uint32_t*)&s0;
            qfh[dk][1] = *(uint32_t*)&s1;
            qfh[dk][2] = *(uint32_t*)&s2;
            qfh[dk][3] = *(uint32_t*)&s3;
            t0 = qlg[r0i + dk * 8 + tig];
            t1 = qlg[r1i + dk * 8 + tig];
            t2 = qlg[r0i + dk * 8 + tig + 4];
            t3 = qlg[r1i + dk * 8 + tig + 4];
            s0 = __hmul2(*(__half2*)&t0, c2);
            s1 = __hmul2(*(__half2*)&t1, c2);
            s2 = __hmul2(*(__half2*)&t2, c2);
            s3 = __hmul2(*(__half2*)&t3, c2);
            qfl[dk][0] = *(uint32_t*)&s0;
            qfl[dk][1] = *(uint32_t*)&s1;
            qfl[dk][2] = *(uint32_t*)&s2;
            qfl[dk][3] = *(uint32_t*)&s3;
        }
    }

    float o[8][4];
#pragma unroll
    for (int nt = 0; nt < 8; nt++)
#pragma unroll
        for (int e = 0; e < 4; e++) o[nt][e] = 0.f;
    float mrow[2] = {-1e30f, -1e30f};
    float lrow[2] = {0.f, 0.f};

    for (int kt = 0; kt <= ktmax; kt++) {
        const int s = kt & 1;
        if (kt == ktmax) { CP_WAIT0(); } else { CP_WAIT1(); }
        __syncthreads();

        const uint32_t* Ks = Stg + s * ATT_STG_U32;
        const uint32_t* Vt = Ks + 64 * AST;
        const int k0 = kt * 64;

        // ---- S = Q K^T (2-pass)
        float sfr[8][4];
#pragma unroll
        for (int nt = 0; nt < 8; nt++)
#pragma unroll
            for (int e = 0; e < 4; e++) sfr[nt][e] = 0.f;

#pragma unroll
        for (int dk = 0; dk < 4; dk++) {
            uint32_t kf[8][2];
#pragma unroll
            for (int nt = 0; nt < 8; nt++) {
                int kn = nt * 8 + gr;
                kf[nt][0] = Ks[kn * AST + dk * 8 + tig];
                kf[nt][1] = Ks[kn * AST + dk * 8 + tig + 4];
            }
#pragma unroll
            for (int nt = 0; nt < 8; nt++)
                mma_f16(sfr[nt], qfh[dk], kf[nt]);
#pragma unroll
            for (int nt = 0; nt < 8; nt++)
                mma_f16(sfr[nt], qfl[dk], kf[nt]);
        }

        // ---- causal mask (only near the diagonal)
        if (k0 + 63 > q0 + m0) {
#pragma unroll
            for (int nt = 0; nt < 8; nt++)
#pragma unroll
                for (int e = 0; e < 4; e++) {
                    int rg = q0 + m0 + gr + (e >> 1) * 8;
                    int cg = k0 + nt * 8 + 2 * tig + (e & 1);
                    if (cg > rg) sfr[nt][e] = -1e30f;
                }
        }

        // ---- online softmax (thread rows: gr, gr+8); p kept in sfr
        float mx0 = -1e30f, mx1 = -1e30f;
#pragma unroll
        for (int nt = 0; nt < 8; nt++) {
            mx0 = fmaxf(mx0, fmaxf(sfr[nt][0], sfr[nt][1]));
            mx1 = fmaxf(mx1, fmaxf(sfr[nt][2], sfr[nt][3]));
        }
        mx0 = fmaxf(mx0, __shfl_xor_sync(0xffffffffu, mx0, 1));
        mx0 = fmaxf(mx0, __shfl_xor_sync(0xffffffffu, mx0, 2));
        mx1 = fmaxf(mx1, __shfl_xor_sync(0xffffffffu, mx1, 1));
        mx1 = fmaxf(mx1, __shfl_xor_sync(0xffffffffu, mx1, 2));

        float nm0 = fmaxf(mrow[0], mx0);
        float nm1 = fmaxf(mrow[1], mx1);
        float f0  = __expf(mrow[0] - nm0);
        float f1  = __expf(mrow[1] - nm1);

        float ps0 = 0.f, ps1 = 0.f;
#pragma unroll
        for (int nt = 0; nt < 8; nt++) {
            sfr[nt][0] = __expf(sfr[nt][0] - nm0);
            sfr[nt][1] = __expf(sfr[nt][1] - nm0);
            sfr[nt][2] = __expf(sfr[nt][2] - nm1);
            sfr[nt][3] = __expf(sfr[nt][3] - nm1);
            ps0 += sfr[nt][0] + sfr[nt][1];
            ps1 += sfr[nt][2] + sfr[nt][3];
        }
        ps0 += __shfl_xor_sync(0xffffffffu, ps0, 1);
        ps0 += __shfl_xor_sync(0xffffffffu, ps0, 2);
        ps1 += __shfl_xor_sync(0xffffffffu, ps1, 1);
        ps1 += __shfl_xor_sync(0xffffffffu, ps1, 2);

        lrow[0] = lrow[0] * f0 + ps0;
        lrow[1] = lrow[1] * f1 + ps1;
        mrow[0] = nm0;
        mrow[1] = nm1;
#pragma unroll
        for (int nt = 0; nt < 8; nt++) {
            o[nt][0] *= f0; o[nt][1] *= f0;
            o[nt][2] *= f1; o[nt][3] *= f1;
        }

        // ---- O += P V (2-pass), P fragments built register-direct from sfr
#pragma unroll
        for (int kk = 0; kk < 4; kk++) {
            uint32_t pfh[4], pfl[4];
            splitpackh(sfr[2 * kk    ][0], sfr[2 * kk    ][1], pfh[0], pfl[0]);
            splitpackh(sfr[2 * kk    ][2], sfr[2 * kk    ][3], pfh[1], pfl[1]);
            splitpackh(sfr[2 * kk + 1][0], sfr[2 * kk + 1][1], pfh[2], pfl[2]);
            splitpackh(sfr[2 * kk + 1][2], sfr[2 * kk + 1][3], pfh[3], pfl[3]);
            uint32_t vf[8][2];
#pragma unroll
            for (int nt = 0; nt < 8; nt++) {
                int dn = nt * 8 + gr;
                vf[nt][0] = Vt[dn * AST + kk * 8 + tig];
                vf[nt][1] = Vt[dn * AST + kk * 8 + tig + 4];
            }
#pragma unroll
            for (int nt = 0; nt < 8; nt++)
                mma_f16(o[nt], pfh, vf[nt]);
#pragma unroll
            for (int nt = 0; nt < 8; nt++)
                mma_f16(o[nt], pfl, vf[nt]);
        }
        __syncthreads();     // all warps done with stage s
        if (kt + 2 <= ktmax) { loadKV(s, kt + 2); CP_COMMIT(); }
    }

    // ---- normalize, split, store to g_ao (fp16 hi/lo, [B*T, C])
    float inv0 = 1.0f / lrow[0];
    float inv1 = 1.0f / lrow[1];
    int r0 = q0 + m0 + gr;
    uint32_t* aoh = (uint32_t*)g_aoh;
    uint32_t* aol = (uint32_t*)g_aol;
#pragma unroll
    for (int nt = 0; nt < 8; nt++) {
        size_t cu = (size_t)h * 32 + nt * 4 + tig;   // u32 col
        uint32_t hp, lp;
        splitpackh(o[nt][0] * inv0, o[nt][1] * inv0, hp, lp);
        aoh[(size_t)(b * SEQ + r0) * (EMBED / 2) + cu] = hp;
        aol[(size_t)(b * SEQ + r0) * (EMBED / 2) + cu] = lp;
        splitpackh(o[nt][2] * inv1, o[nt][3] * inv1, hp, lp);
        aoh[(size_t)(b * SEQ + r0 + 8) * (EMBED / 2) + cu] = hp;
        aol[(size_t)(b * SEQ + r0 + 8) * (EMBED / 2) + cu] = lp;
    }
}

// ---------------------------------------------------------------------------
extern "C" void kernel_launch(void* const* d_in, const int* in_sizes, int n_in,
                              void* d_out, int out_size)
{
    const float* x      = (const float*)d_in[0];   // [4,2048,1024]
    const float* W_qkv  = (const float*)d_in[1];   // [3072,1024]
    const float* W_proj = (const float*)d_in[2];   // [1024,1024]
    float* out = (float*)d_out;                    // [4,2048,1024]

    __half *xh, *xl, *wq, *wp, *aoh, *aol;
    cudaGetSymbolAddress((void**)&xh,  g_xh);
    cudaGetSymbolAddress((void**)&xl,  g_xl);
    cudaGetSymbolAddress((void**)&wq,  g_wq);
    cudaGetSymbolAddress((void**)&wp,  g_wp);
    cudaGetSymbolAddress((void**)&aoh, g_aoh);
    cudaGetSymbolAddress((void**)&aol, g_aol);

    // 0) prep: x split hi/lo; weights single fp16
    {
        int n1 = MROWS * EMBED / 4, n2 = 3 * EMBED * EMBED / 4, n3 = EMBED * EMBED / 4;
        split_f32h<<<(n1 + 255) / 256, 256>>>((const float4*)x, (uint2*)xh, (uint2*)xl, n1);
        cvt_f32h<<<(n2 + 255) / 256, 256>>>((const float4*)W_qkv, (uint2*)wq, n2);
        cvt_f32h<<<(n3 + 255) / 256, 256>>>((const float4*)W_proj, (uint2*)wp, n3);
    }

    // 1) QKV projection with scatter epilogue
    {
        cudaFuncSetAttribute((const void*)gemm_h2<1>,
                             cudaFuncAttributeMaxDynamicSharedMemorySize, GEMM_SMEM);
        dim3 grid(3 * EMBED / 128, MROWS / 128);
        gemm_h2<1><<<grid, 256, GEMM_SMEM>>>(xh, xl, wq, nullptr, EMBED, 3 * EMBED);
    }

    // 2) causal flash attention -> g_ao (split fp16)
    {
        cudaFuncSetAttribute((const void*)attn_h2,
                             cudaFuncAttributeMaxDynamicSharedMemorySize, ATT_SMEM);
        dim3 grid(SEQ / 128, BATCH * NHEAD);
        attn_h2<<<grid, 256, ATT_SMEM>>>();
    }

    // 3) output projection -> d_out (fp32)
    {
        cudaFuncSetAttribute((const void*)gemm_h2<0>,
                             cudaFuncAttributeMaxDynamicSharedMemorySize, GEMM_SMEM);
        dim3 grid(EMBED / 128, MROWS / 128);
        gemm_h2<0><<<grid, 256, GEMM_SMEM>>>(aoh, aol, wp, out, EMBED, EMBED);
    }
}

// round 12
// speedup vs baseline: 1.5306x; 1.0384x over previous
#include <cuda_runtime.h>
#include <cuda_fp16.h>
#include <cstdint>

// Problem constants
#define EMBED   1024
#define NHEAD   16
#define HDIM    64
#define BATCH   4
#define SEQ     2048
#define MROWS   (BATCH * SEQ)                 // 8192
#define QKVN    (BATCH * NHEAD * SEQ * HDIM)  // 8388608

// ---------------------------------------------------------------------------
// Persistent scratch (fp16; activations split hi/lo, weights/K/V single fp16)
// ---------------------------------------------------------------------------
__device__ __align__(16) __half g_xh [MROWS * EMBED];
__device__ __align__(16) __half g_xl [MROWS * EMBED];
__device__ __align__(16) __half g_wq [3 * EMBED * EMBED];
__device__ __align__(16) __half g_wp [EMBED * EMBED];
__device__ __align__(16) __half g_qh [QKVN];   // [B,H,T,D] split
__device__ __align__(16) __half g_ql [QKVN];
__device__ __align__(16) __half g_k  [QKVN];   // [B,H,T,D] single
__device__ __align__(16) __half g_vt [QKVN];   // [B,H,D,T] single (transposed)
__device__ __align__(16) __half g_aoh[MROWS * EMBED];   // [B*T, C] split
__device__ __align__(16) __half g_aol[MROWS * EMBED];

// ---------------------------------------------------------------------------
// helpers
// ---------------------------------------------------------------------------
__device__ __forceinline__ void mma_f16(float* c, const uint32_t* a, const uint32_t* b) {
    asm volatile(
        "mma.sync.aligned.m16n8k16.row.col.f32.f16.f16.f32 "
        "{%0,%1,%2,%3}, {%4,%5,%6,%7}, {%8,%9}, {%0,%1,%2,%3};"
        : "+f"(c[0]), "+f"(c[1]), "+f"(c[2]), "+f"(c[3])
        : "r"(a[0]), "r"(a[1]), "r"(a[2]), "r"(a[3]), "r"(b[0]), "r"(b[1]));
}
__device__ __forceinline__ void ldsm_x4(uint32_t& r0, uint32_t& r1,
                                        uint32_t& r2, uint32_t& r3, uint32_t addr) {
    asm volatile("ldmatrix.sync.aligned.m8n8.x4.shared.b16 {%0,%1,%2,%3}, [%4];"
        : "=r"(r0), "=r"(r1), "=r"(r2), "=r"(r3) : "r"(addr));
}
__device__ __forceinline__ uint32_t packh(float x0, float x1) {
    __half2 h = __floats2half2_rn(x0, x1);
    return *(uint32_t*)&h;
}
__device__ __forceinline__ void splitpackh(float x0, float x1, uint32_t& hp, uint32_t& lp) {
    __half h0 = __float2half_rn(x0);
    __half h1 = __float2half_rn(x1);
    __half l0 = __float2half_rn(x0 - __half2float(h0));
    __half l1 = __float2half_rn(x1 - __half2float(h1));
    hp = (uint32_t)__half_as_ushort(h0) | ((uint32_t)__half_as_ushort(h1) << 16);
    lp = (uint32_t)__half_as_ushort(l0) | ((uint32_t)__half_as_ushort(l1) << 16);
}
__device__ __forceinline__ void cpasync16(void* s, const void* g) {
    uint32_t sa = (uint32_t)__cvta_generic_to_shared(s);
    asm volatile("cp.async.cg.shared.global [%0], [%1], 16;\n" :: "r"(sa), "l"(g));
}
#define CP_COMMIT() asm volatile("cp.async.commit_group;\n" ::: "memory")
#define CP_WAIT1()  asm volatile("cp.async.wait_group 1;\n"  ::: "memory")
#define CP_WAIT0()  asm volatile("cp.async.wait_group 0;\n"  ::: "memory")

// ---------------------------------------------------------------------------
// prep kernels
// ---------------------------------------------------------------------------
__global__ void split_f32h(const float4* __restrict__ src,
                           uint2* __restrict__ hi,
                           uint2* __restrict__ lo, int n4)
{
    int i = blockIdx.x * blockDim.x + threadIdx.x;
    if (i < n4) {
        float4 v = src[i];
        uint32_t h0, l0, h1, l1;
        splitpackh(v.x, v.y, h0, l0);
        splitpackh(v.z, v.w, h1, l1);
        hi[i] = make_uint2(h0, h1);
        lo[i] = make_uint2(l0, l1);
    }
}
__global__ void cvt_f32h(const float4* __restrict__ src,
                         uint2* __restrict__ dst, int n4)
{
    int i = blockIdx.x * blockDim.x + threadIdx.x;
    if (i < n4) {
        float4 v = src[i];
        dst[i] = make_uint2(packh(v.x, v.y), packh(v.z, v.w));
    }
}

// ---------------------------------------------------------------------------
// 2-pass fp16 GEMM:  C = A @ B^T.  A:[M,K] rm hi/lo (exact), B:[N,K] rm fp16.
// Block 128x128, kTile 32 (fp16), 256 threads (8 warps, warp tile 32x64).
// 2-stage cp.async pipeline. Fragments via ldmatrix.x4 (conflict-free: row
// stride 80B covers all 32 banks across 8 rows). MMAs: Ah*B + Al*B.
// MODE 0: fp32 store C.  MODE 1: QKV scatter epilogue.
// ---------------------------------------------------------------------------
#define GST    20                          // smem row stride in u32 (16 data + 4 pad)
#define GCOMP  (128 * GST)                 // u32 per component per stage
#define GSTAGE (3 * GCOMP)                 // Ah, Al, B
#define GEMM_SMEM (2 * GSTAGE * 4)         // 61440 bytes

template <int MODE>
__global__ void __launch_bounds__(256, 2)
gemm_h2(const __half* __restrict__ Ah, const __half* __restrict__ Al,
        const __half* __restrict__ B,
        float* __restrict__ C, int K, int N)
{
    extern __shared__ uint32_t smu[];
    const uint32_t smb = (uint32_t)__cvta_generic_to_shared(smu);

    const int tid  = threadIdx.x;
    const int lane = tid & 31;
    const int w    = tid >> 5;
    const int gr   = lane >> 2;
    const int tig  = lane & 3;
    const int wm   = w & 3;              // 32-row quadrant
    const int wn   = w >> 2;             // 64-col half

    // ldmatrix lane mappings
    const int lrowA = (lane & 7) + ((lane >> 3) & 1) * 8;   // A: row within m16
    const int lcolA = (lane >> 4) * 4;                       // A: +u32 col for k8-15
    const int lrowB = ((lane >> 4) & 1) * 8 + (lane & 7);    // B: row within n16 pair
    const int lcolB = ((lane >> 3) & 1) * 4;                 // B: +u32 col for k8-15

    const int row0 = blockIdx.y * 128;
    const int col0 = blockIdx.x * 128;

    float acc[2][8][4];
#pragma unroll
    for (int i = 0; i < 2; i++)
#pragma unroll
        for (int j = 0; j < 8; j++)
#pragma unroll
            for (int e = 0; e < 4; e++) acc[i][j][e] = 0.f;

    // stage loader: per component 128 rows x 32 fp16 (4 x 16B chunks per row)
    auto loadTile = [&](int s, int kt) {
        uint32_t* st = smu + (size_t)s * GSTAGE;
#pragma unroll
        for (int p = 0; p < 2; p++) {
            int c   = tid + 256 * p;         // 0..511
            int row = c >> 2;
            int ch  = c & 3;
            uint32_t* d0 = st + row * GST + ch * 4;
            size_t ga = (size_t)(row0 + row) * K + kt + ch * 8;
            size_t gb = (size_t)(col0 + row) * K + kt + ch * 8;
            cpasync16(d0,             Ah + ga);
            cpasync16(d0 + GCOMP,     Al + ga);
            cpasync16(d0 + 2 * GCOMP, B + gb);
        }
    };

    const int nk = K / 32;
    loadTile(0, 0);  CP_COMMIT();
    loadTile(1, 32); CP_COMMIT();

    for (int t = 0; t < nk; t++) {
        const int s = t & 1;
        if (t >= nk - 2) { CP_WAIT0(); } else { CP_WAIT1(); }
        __syncthreads();

        const uint32_t stb = smb + (uint32_t)s * GSTAGE * 4;

#pragma unroll
        for (int ks = 0; ks < 2; ks++) {
            const int base = ks * 8;
            uint32_t ah[2][4], al_[2][4];
#pragma unroll
            for (int mt = 0; mt < 2; mt++) {
                uint32_t aoff = ((wm * 32 + mt * 16 + lrowA) * GST + base + lcolA) * 4;
                ldsm_x4(ah[mt][0],  ah[mt][1],  ah[mt][2],  ah[mt][3],  stb + aoff);
                ldsm_x4(al_[mt][0], al_[mt][1], al_[mt][2], al_[mt][3],
                        stb + GCOMP * 4 + aoff);
            }
            uint32_t bf[8][2];
#pragma unroll
            for (int j = 0; j < 4; j++) {
                uint32_t boff = ((wn * 64 + j * 16 + lrowB) * GST + base + lcolB) * 4;
                ldsm_x4(bf[2 * j][0], bf[2 * j][1], bf[2 * j + 1][0], bf[2 * j + 1][1],
                        stb + 2 * GCOMP * 4 + boff);
            }
#pragma unroll
            for (int mt = 0; mt < 2; mt++)
#pragma unroll
                for (int nt = 0; nt < 8; nt++)
                    mma_f16(acc[mt][nt], ah[mt], bf[nt]);
#pragma unroll
            for (int mt = 0; mt < 2; mt++)
#pragma unroll
                for (int nt = 0; nt < 8; nt++)
                    mma_f16(acc[mt][nt], al_[mt], bf[nt]);
        }
        __syncthreads();
        if (t + 2 < nk) { loadTile(s, (t + 2) * 32); CP_COMMIT(); }
    }

    // ---- epilogue
#pragma unroll
    for (int mt = 0; mt < 2; mt++) {
#pragma unroll
        for (int e2 = 0; e2 < 2; e2++) {
            int r = row0 + wm * 32 + mt * 16 + gr + e2 * 8;
#pragma unroll
            for (int nt = 0; nt < 8; nt++) {
                int n = col0 + wn * 64 + nt * 8 + 2 * tig;
                float v0 = acc[mt][nt][e2 * 2 + 0];
                float v1 = acc[mt][nt][e2 * 2 + 1];
                if (MODE == 0) {
                    *(float2*)&C[(size_t)r * N + n] = make_float2(v0, v1);
                } else {
                    int b   = r >> 11;            // / SEQ
                    int tk  = r & (SEQ - 1);
                    int sec = n >> 10;
                    int c   = n & 1023;
                    int h   = c >> 6;
                    int d   = c & 63;
                    int bh_ = b * NHEAD + h;
                    if (sec == 0) {
                        // Q: split hi/lo (exact operand for S)
                        uint32_t hp, lp;
                        splitpackh(v0, v1, hp, lp);
                        size_t i2 = (((size_t)bh_ * SEQ + tk) * HDIM + d) >> 1;
                        ((uint32_t*)g_qh)[i2] = hp;
                        ((uint32_t*)g_ql)[i2] = lp;
                    } else if (sec == 1) {
                        // K: single fp16
                        size_t i2 = (((size_t)bh_ * SEQ + tk) * HDIM + d) >> 1;
                        ((uint32_t*)g_k)[i2] = packh(v0, v1);
                    } else {
                        // V: single fp16, transposed [B,H,D,T]
                        size_t i0 = ((size_t)bh_ * HDIM + d) * SEQ + tk;
                        g_vt[i0]       = __float2half_rn(v0);
                        g_vt[i0 + SEQ] = __float2half_rn(v1);
                    }
                }
            }
        }
    }
}

// ---------------------------------------------------------------------------
// Causal flash attention, 2-pass fp16 mma.sync. Br=128, Bc=64, D=64.
// 256 threads = 8 warps; warp w owns q rows [16w, 16w+16).
// Q fragments from gmem (L2-resident), pre-scaled by 0.125.
// K/V fragments via ldmatrix.x4 (conflict-free: 144B row stride).
// P built register-direct from the S fragments. 2-stage cp.async prefetch.
// Heavy q-blocks scheduled first (LPT). grid: (SEQ/128, B*H)
// ---------------------------------------------------------------------------
#define AST 36                                   // smem row stride in u32
#define ATT_STG_U32 (2 * 64 * AST)               // Ks, Vt per stage
#define ATT_SMEM (2 * ATT_STG_U32 * 4)           // 36864 bytes

__global__ void __launch_bounds__(256, 2)
attn_h2()
{
    extern __shared__ uint32_t smu[];
    const uint32_t smb = (uint32_t)__cvta_generic_to_shared(smu);
    uint32_t* Stg = smu;                    // 2 stages of {Ks, Vt}

    const int tid  = threadIdx.x;
    const int lane = tid & 31;
    const int w    = tid >> 5;
    const int gr   = lane >> 2;
    const int tig  = lane & 3;
    const int m0   = w * 16;

    // ldmatrix lane mapping for B-operand pairs (K and V tiles)
    const int lrowB = ((lane >> 4) & 1) * 8 + (lane & 7);
    const int lcolB = ((lane >> 3) & 1) * 4;

    const int qb = gridDim.x - 1 - blockIdx.x;   // longest-processing-time first
    const int bh = blockIdx.y;
    const int b  = bh >> 4;
    const int h  = bh & 15;
    const int q0 = qb * 128;

    const size_t bhoff = (size_t)bh * SEQ * HDIM;
    const size_t vtoff = (size_t)bh * HDIM * SEQ;

    // K/V prefetch (cp.async, 2 stages)
    auto loadKV = [&](int s, int kt) {
        const int k0 = kt * 64;
        uint32_t* st = Stg + s * ATT_STG_U32;
        for (int i = tid; i < 64 * 8; i += 256) {
            int row = i >> 3, ch = i & 7;
            uint32_t* d = st + row * AST + ch * 4;
            size_t gk = bhoff + (size_t)(k0 + row) * HDIM + ch * 8;
            size_t gv = vtoff + (size_t)row * SEQ + k0 + ch * 8;
            cpasync16(d,            g_k  + gk);
            cpasync16(d + 64 * AST, g_vt + gv);
        }
    };

    const int ktmax = 2 * qb + 1;          // >= 1 always
    loadKV(0, 0); CP_COMMIT();
    loadKV(1, 1); CP_COMMIT();

    // ---- Q fragments straight from gmem, pre-scaled by 0.125 (exact in fp16)
    uint32_t qfh[4][4], qfl[4][4];
    {
        const __half2 c2 = __floats2half2_rn(0.125f, 0.125f);
        const uint32_t* qhg = (const uint32_t*)(g_qh + bhoff + (size_t)q0 * HDIM);
        const uint32_t* qlg = (const uint32_t*)(g_ql + bhoff + (size_t)q0 * HDIM);
        const int r0i = (m0 + gr) * 32;          // u32 row stride = HDIM/2
        const int r1i = (m0 + gr + 8) * 32;
#pragma unroll
        for (int dk = 0; dk < 4; dk++) {
            uint32_t t0 = qhg[r0i + dk * 8 + tig];
            uint32_t t1 = qhg[r1i + dk * 8 + tig];
            uint32_t t2 = qhg[r0i + dk * 8 + tig + 4];
            uint32_t t3 = qhg[r1i + dk * 8 + tig + 4];
            __half2 s0 = __hmul2(*(__half2*)&t0, c2);
            __half2 s1 = __hmul2(*(__half2*)&t1, c2);
            __half2 s2 = __hmul2(*(__half2*)&t2, c2);
            __half2 s3 = __hmul2(*(__half2*)&t3, c2);
            qfh[dk][0] = *(uint32_t*)&s0;
            qfh[dk][1] = *(uint32_t*)&s1;
            qfh[dk][2] = *(uint32_t*)&s2;
            qfh[dk][3] = *(uint32_t*)&s3;
            t0 = qlg[r0i + dk * 8 + tig];
            t1 = qlg[r1i + dk * 8 + tig];
            t2 = qlg[r0i + dk * 8 + tig + 4];
            t3 = qlg[r1i + dk * 8 + tig + 4];
            s0 = __hmul2(*(__half2*)&t0, c2);
            s1 = __hmul2(*(__half2*)&t1, c2);
            s2 = __hmul2(*(__half2*)&t2, c2);
            s3 = __hmul2(*(__half2*)&t3, c2);
            qfl[dk][0] = *(uint32_t*)&s0;
            qfl[dk][1] = *(uint32_t*)&s1;
            qfl[dk][2] = *(uint32_t*)&s2;
            qfl[dk][3] = *(uint32_t*)&s3;
        }
    }

    float o[8][4];
#pragma unroll
    for (int nt = 0; nt < 8; nt++)
#pragma unroll
        for (int e = 0; e < 4; e++) o[nt][e] = 0.f;
    float mrow[2] = {-1e30f, -1e30f};
    float lrow[2] = {0.f, 0.f};

    for (int kt = 0; kt <= ktmax; kt++) {
        const int s = kt & 1;
        if (kt == ktmax) { CP_WAIT0(); } else { CP_WAIT1(); }
        __syncthreads();

        const uint32_t ksb = smb + (uint32_t)s * ATT_STG_U32 * 4;
        const uint32_t vtb = ksb + 64 * AST * 4;
        const int k0 = kt * 64;

        // ---- S = Q K^T (2-pass), K fragments via ldmatrix
        float sfr[8][4];
#pragma unroll
        for (int nt = 0; nt < 8; nt++)
#pragma unroll
            for (int e = 0; e < 4; e++) sfr[nt][e] = 0.f;

#pragma unroll
        for (int dk = 0; dk < 4; dk++) {
            uint32_t kf[8][2];
#pragma unroll
            for (int j = 0; j < 4; j++) {
                uint32_t koff = ((j * 16 + lrowB) * AST + dk * 8 + lcolB) * 4;
                ldsm_x4(kf[2 * j][0], kf[2 * j][1], kf[2 * j + 1][0], kf[2 * j + 1][1],
                        ksb + koff);
            }
#pragma unroll
            for (int nt = 0; nt < 8; nt++)
                mma_f16(sfr[nt], qfh[dk], kf[nt]);
#pragma unroll
            for (int nt = 0; nt < 8; nt++)
                mma_f16(sfr[nt], qfl[dk], kf[nt]);
        }

        // ---- causal mask (only near the diagonal)
        if (k0 + 63 > q0 + m0) {
#pragma unroll
            for (int nt = 0; nt < 8; nt++)
#pragma unroll
                for (int e = 0; e < 4; e++) {
                    int rg = q0 + m0 + gr + (e >> 1) * 8;
                    int cg = k0 + nt * 8 + 2 * tig + (e & 1);
                    if (cg > rg) sfr[nt][e] = -1e30f;
                }
        }

        // ---- online softmax (thread rows: gr, gr+8); p kept in sfr
        float mx0 = -1e30f, mx1 = -1e30f;
#pragma unroll
        for (int nt = 0; nt < 8; nt++) {
            mx0 = fmaxf(mx0, fmaxf(sfr[nt][0], sfr[nt][1]));
            mx1 = fmaxf(mx1, fmaxf(sfr[nt][2], sfr[nt][3]));
        }
        mx0 = fmaxf(mx0, __shfl_xor_sync(0xffffffffu, mx0, 1));
        mx0 = fmaxf(mx0, __shfl_xor_sync(0xffffffffu, mx0, 2));
        mx1 = fmaxf(mx1, __shfl_xor_sync(0xffffffffu, mx1, 1));
        mx1 = fmaxf(mx1, __shfl_xor_sync(0xffffffffu, mx1, 2));

        float nm0 = fmaxf(mrow[0], mx0);
        float nm1 = fmaxf(mrow[1], mx1);
        float f0  = __expf(mrow[0] - nm0);
        float f1  = __expf(mrow[1] - nm1);

        float ps0 = 0.f, ps1 = 0.f;
#pragma unroll
        for (int nt = 0; nt < 8; nt++) {
            sfr[nt][0] = __expf(sfr[nt][0] - nm0);
            sfr[nt][1] = __expf(sfr[nt][1] - nm0);
            sfr[nt][2] = __expf(sfr[nt][2] - nm1);
            sfr[nt][3] = __expf(sfr[nt][3] - nm1);
            ps0 += sfr[nt][0] + sfr[nt][1];
            ps1 += sfr[nt][2] + sfr[nt][3];
        }
        ps0 += __shfl_xor_sync(0xffffffffu, ps0, 1);
        ps0 += __shfl_xor_sync(0xffffffffu, ps0, 2);
        ps1 += __shfl_xor_sync(0xffffffffu, ps1, 1);
        ps1 += __shfl_xor_sync(0xffffffffu, ps1, 2);

        lrow[0] = lrow[0] * f0 + ps0;
        lrow[1] = lrow[1] * f1 + ps1;
        mrow[0] = nm0;
        mrow[1] = nm1;
#pragma unroll
        for (int nt = 0; nt < 8; nt++) {
            o[nt][0] *= f0; o[nt][1] *= f0;
            o[nt][2] *= f1; o[nt][3] *= f1;
        }

        // ---- O += P V (2-pass), P register-direct, V via ldmatrix
#pragma unroll
        for (int kk = 0; kk < 4; kk++) {
            uint32_t pfh[4], pfl[4];
            splitpackh(sfr[2 * kk    ][0], sfr[2 * kk    ][1], pfh[0], pfl[0]);
            splitpackh(sfr[2 * kk    ][2], sfr[2 * kk    ][3], pfh[1], pfl[1]);
            splitpackh(sfr[2 * kk + 1][0], sfr[2 * kk + 1][1], pfh[2], pfl[2]);
            splitpackh(sfr[2 * kk + 1][2], sfr[2 * kk + 1][3], pfh[3], pfl[3]);
            uint32_t vf[8][2];
#pragma unroll
            for (int j = 0; j < 4; j++) {
                uint32_t voff = ((j * 16 + lrowB) * AST + kk * 8 + lcolB) * 4;
                ldsm_x4(vf[2 * j][0], vf[2 * j][1], vf[2 * j + 1][0], vf[2 * j + 1][1],
                        vtb + voff);
            }
#pragma unroll
            for (int nt = 0; nt < 8; nt++)
                mma_f16(o[nt], pfh, vf[nt]);
#pragma unroll
            for (int nt = 0; nt < 8; nt++)
                mma_f16(o[nt], pfl, vf[nt]);
        }
        __syncthreads();     // all warps done with stage s
        if (kt + 2 <= ktmax) { loadKV(s, kt + 2); CP_COMMIT(); }
    }

    // ---- normalize, split, store to g_ao (fp16 hi/lo, [B*T, C])
    float inv0 = 1.0f / lrow[0];
    float inv1 = 1.0f / lrow[1];
    int r0 = q0 + m0 + gr;
    uint32_t* aoh = (uint32_t*)g_aoh;
    uint32_t* aol = (uint32_t*)g_aol;
#pragma unroll
    for (int nt = 0; nt < 8; nt++) {
        size_t cu = (size_t)h * 32 + nt * 4 + tig;   // u32 col
        uint32_t hp, lp;
        splitpackh(o[nt][0] * inv0, o[nt][1] * inv0, hp, lp);
        aoh[(size_t)(b * SEQ + r0) * (EMBED / 2) + cu] = hp;
        aol[(size_t)(b * SEQ + r0) * (EMBED / 2) + cu] = lp;
        splitpackh(o[nt][2] * inv1, o[nt][3] * inv1, hp, lp);
        aoh[(size_t)(b * SEQ + r0 + 8) * (EMBED / 2) + cu] = hp;
        aol[(size_t)(b * SEQ + r0 + 8) * (EMBED / 2) + cu] = lp;
    }
}

// ---------------------------------------------------------------------------
extern "C" void kernel_launch(void* const* d_in, const int* in_sizes, int n_in,
                              void* d_out, int out_size)
{
    const float* x      = (const float*)d_in[0];   // [4,2048,1024]
    const float* W_qkv  = (const float*)d_in[1];   // [3072,1024]
    const float* W_proj = (const float*)d_in[2];   // [1024,1024]
    float* out = (float*)d_out;                    // [4,2048,1024]

    __half *xh, *xl, *wq, *wp, *aoh, *aol;
    cudaGetSymbolAddress((void**)&xh,  g_xh);
    cudaGetSymbolAddress((void**)&xl,  g_xl);
    cudaGetSymbolAddress((void**)&wq,  g_wq);
    cudaGetSymbolAddress((void**)&wp,  g_wp);
    cudaGetSymbolAddress((void**)&aoh, g_aoh);
    cudaGetSymbolAddress((void**)&aol, g_aol);

    // 0) prep: x split hi/lo; weights single fp16
    {
        int n1 = MROWS * EMBED / 4, n2 = 3 * EMBED * EMBED / 4, n3 = EMBED * EMBED / 4;
        split_f32h<<<(n1 + 255) / 256, 256>>>((const float4*)x, (uint2*)xh, (uint2*)xl, n1);
        cvt_f32h<<<(n2 + 255) / 256, 256>>>((const float4*)W_qkv, (uint2*)wq, n2);
        cvt_f32h<<<(n3 + 255) / 256, 256>>>((const float4*)W_proj, (uint2*)wp, n3);
    }

    // 1) QKV projection with scatter epilogue
    {
        cudaFuncSetAttribute((const void*)gemm_h2<1>,
                             cudaFuncAttributeMaxDynamicSharedMemorySize, GEMM_SMEM);
        dim3 grid(3 * EMBED / 128, MROWS / 128);
        gemm_h2<1><<<grid, 256, GEMM_SMEM>>>(xh, xl, wq, nullptr, EMBED, 3 * EMBED);
    }

    // 2) causal flash attention -> g_ao (split fp16)
    {
        cudaFuncSetAttribute((const void*)attn_h2,
                             cudaFuncAttributeMaxDynamicSharedMemorySize, ATT_SMEM);
        dim3 grid(SEQ / 128, BATCH * NHEAD);
        attn_h2<<<grid, 256, ATT_SMEM>>>();
    }

    // 3) output projection -> d_out (fp32)
    {
        cudaFuncSetAttribute((const void*)gemm_h2<0>,
                             cudaFuncAttributeMaxDynamicSharedMemorySize, GEMM_SMEM);
        dim3 grid(EMBED / 128, MROWS / 128);
        gemm_h2<0><<<grid, 256, GEMM_SMEM>>>(aoh, aol, wp, out, EMBED, EMBED);
    }
}

// round 13
// speedup vs baseline: 2.0753x; 1.3559x over previous
#include <cuda_runtime.h>
#include <cuda_fp16.h>
#include <cstdint>

// Problem constants
#define EMBED   1024
#define NHEAD   16
#define HDIM    64
#define BATCH   4
#define SEQ     2048
#define MROWS   (BATCH * SEQ)                 // 8192
#define QKVN    (BATCH * NHEAD * SEQ * HDIM)  // 8388608

// ---------------------------------------------------------------------------
// Persistent scratch (fp16). Q kept split hi/lo (exact S operand); everything
// else single fp16.
// ---------------------------------------------------------------------------
__device__ __align__(16) __half g_x  [MROWS * EMBED];
__device__ __align__(16) __half g_wq [3 * EMBED * EMBED];
__device__ __align__(16) __half g_wp [EMBED * EMBED];
__device__ __align__(16) __half g_qh [QKVN];   // [B,H,T,D] split
__device__ __align__(16) __half g_ql [QKVN];
__device__ __align__(16) __half g_k  [QKVN];   // [B,H,T,D] single
__device__ __align__(16) __half g_vt [QKVN];   // [B,H,D,T] single (transposed)
__device__ __align__(16) __half g_ao [MROWS * EMBED];   // [B*T, C] single

// ---------------------------------------------------------------------------
// helpers
// ---------------------------------------------------------------------------
__device__ __forceinline__ void mma_f16(float* c, const uint32_t* a, const uint32_t* b) {
    asm volatile(
        "mma.sync.aligned.m16n8k16.row.col.f32.f16.f16.f32 "
        "{%0,%1,%2,%3}, {%4,%5,%6,%7}, {%8,%9}, {%0,%1,%2,%3};"
        : "+f"(c[0]), "+f"(c[1]), "+f"(c[2]), "+f"(c[3])
        : "r"(a[0]), "r"(a[1]), "r"(a[2]), "r"(a[3]), "r"(b[0]), "r"(b[1]));
}
__device__ __forceinline__ void ldsm_x4(uint32_t& r0, uint32_t& r1,
                                        uint32_t& r2, uint32_t& r3, uint32_t addr) {
    asm volatile("ldmatrix.sync.aligned.m8n8.x4.shared.b16 {%0,%1,%2,%3}, [%4];"
        : "=r"(r0), "=r"(r1), "=r"(r2), "=r"(r3) : "r"(addr));
}
__device__ __forceinline__ uint32_t packh(float x0, float x1) {
    __half2 h = __floats2half2_rn(x0, x1);
    return *(uint32_t*)&h;
}
__device__ __forceinline__ void splitpackh(float x0, float x1, uint32_t& hp, uint32_t& lp) {
    __half h0 = __float2half_rn(x0);
    __half h1 = __float2half_rn(x1);
    __half l0 = __float2half_rn(x0 - __half2float(h0));
    __half l1 = __float2half_rn(x1 - __half2float(h1));
    hp = (uint32_t)__half_as_ushort(h0) | ((uint32_t)__half_as_ushort(h1) << 16);
    lp = (uint32_t)__half_as_ushort(l0) | ((uint32_t)__half_as_ushort(l1) << 16);
}
__device__ __forceinline__ void cpasync16(void* s, const void* g) {
    uint32_t sa = (uint32_t)__cvta_generic_to_shared(s);
    asm volatile("cp.async.cg.shared.global [%0], [%1], 16;\n" :: "r"(sa), "l"(g));
}
#define CP_COMMIT() asm volatile("cp.async.commit_group;\n" ::: "memory")
#define CP_WAIT1()  asm volatile("cp.async.wait_group 1;\n"  ::: "memory")
#define CP_WAIT0()  asm volatile("cp.async.wait_group 0;\n"  ::: "memory")

// ---------------------------------------------------------------------------
// prep kernel: fp32 -> fp16
// ---------------------------------------------------------------------------
__global__ void cvt_f32h(const float4* __restrict__ src,
                         uint2* __restrict__ dst, int n4)
{
    int i = blockIdx.x * blockDim.x + threadIdx.x;
    if (i < n4) {
        float4 v = src[i];
        dst[i] = make_uint2(packh(v.x, v.y), packh(v.z, v.w));
    }
}

// ---------------------------------------------------------------------------
// single-pass fp16 GEMM:  C = A @ B^T.  A:[M,K] rm fp16, B:[N,K] rm fp16.
// Block 128x128, kTile 32 (fp16), 256 threads (8 warps, warp tile 32x64).
// 2-stage cp.async pipeline, fragments via ldmatrix.x4 (conflict-free).
// MODE 0: fp32 store C.  MODE 1: QKV scatter epilogue (Q split hi/lo).
// ---------------------------------------------------------------------------
#define GST    20                          // smem row stride in u32 (16 data + 4 pad)
#define GCOMP  (128 * GST)                 // u32 per component per stage
#define GSTAGE (2 * GCOMP)                 // A, B
#define GEMM_SMEM (2 * GSTAGE * 4)         // 40960 bytes

template <int MODE>
__global__ void __launch_bounds__(256, 2)
gemm_h1(const __half* __restrict__ A, const __half* __restrict__ B,
        float* __restrict__ C, int K, int N)
{
    extern __shared__ uint32_t smu[];
    const uint32_t smb = (uint32_t)__cvta_generic_to_shared(smu);

    const int tid  = threadIdx.x;
    const int lane = tid & 31;
    const int w    = tid >> 5;
    const int gr   = lane >> 2;
    const int tig  = lane & 3;
    const int wm   = w & 3;              // 32-row quadrant
    const int wn   = w >> 2;             // 64-col half

    // ldmatrix lane mappings
    const int lrowA = (lane & 7) + ((lane >> 3) & 1) * 8;
    const int lcolA = (lane >> 4) * 4;
    const int lrowB = ((lane >> 4) & 1) * 8 + (lane & 7);
    const int lcolB = ((lane >> 3) & 1) * 4;

    const int row0 = blockIdx.y * 128;
    const int col0 = blockIdx.x * 128;

    float acc[2][8][4];
#pragma unroll
    for (int i = 0; i < 2; i++)
#pragma unroll
        for (int j = 0; j < 8; j++)
#pragma unroll
            for (int e = 0; e < 4; e++) acc[i][j][e] = 0.f;

    // stage loader: per component 128 rows x 32 fp16 (4 x 16B chunks per row)
    auto loadTile = [&](int s, int kt) {
        uint32_t* st = smu + (size_t)s * GSTAGE;
#pragma unroll
        for (int p = 0; p < 2; p++) {
            int c   = tid + 256 * p;         // 0..511
            int row = c >> 2;
            int ch  = c & 3;
            uint32_t* d0 = st + row * GST + ch * 4;
            size_t ga = (size_t)(row0 + row) * K + kt + ch * 8;
            size_t gb = (size_t)(col0 + row) * K + kt + ch * 8;
            cpasync16(d0,         A + ga);
            cpasync16(d0 + GCOMP, B + gb);
        }
    };

    const int nk = K / 32;
    loadTile(0, 0);  CP_COMMIT();
    loadTile(1, 32); CP_COMMIT();

    for (int t = 0; t < nk; t++) {
        const int s = t & 1;
        if (t >= nk - 2) { CP_WAIT0(); } else { CP_WAIT1(); }
        __syncthreads();

        const uint32_t stb = smb + (uint32_t)s * GSTAGE * 4;

#pragma unroll
        for (int ks = 0; ks < 2; ks++) {
            const int base = ks * 8;
            uint32_t af[2][4];
#pragma unroll
            for (int mt = 0; mt < 2; mt++) {
                uint32_t aoff = ((wm * 32 + mt * 16 + lrowA) * GST + base + lcolA) * 4;
                ldsm_x4(af[mt][0], af[mt][1], af[mt][2], af[mt][3], stb + aoff);
            }
            uint32_t bf[8][2];
#pragma unroll
            for (int j = 0; j < 4; j++) {
                uint32_t boff = ((wn * 64 + j * 16 + lrowB) * GST + base + lcolB) * 4;
                ldsm_x4(bf[2 * j][0], bf[2 * j][1], bf[2 * j + 1][0], bf[2 * j + 1][1],
                        stb + GCOMP * 4 + boff);
            }
#pragma unroll
            for (int mt = 0; mt < 2; mt++)
#pragma unroll
                for (int nt = 0; nt < 8; nt++)
                    mma_f16(acc[mt][nt], af[mt], bf[nt]);
        }
        __syncthreads();
        if (t + 2 < nk) { loadTile(s, (t + 2) * 32); CP_COMMIT(); }
    }

    // ---- epilogue
#pragma unroll
    for (int mt = 0; mt < 2; mt++) {
#pragma unroll
        for (int e2 = 0; e2 < 2; e2++) {
            int r = row0 + wm * 32 + mt * 16 + gr + e2 * 8;
#pragma unroll
            for (int nt = 0; nt < 8; nt++) {
                int n = col0 + wn * 64 + nt * 8 + 2 * tig;
                float v0 = acc[mt][nt][e2 * 2 + 0];
                float v1 = acc[mt][nt][e2 * 2 + 1];
                if (MODE == 0) {
                    *(float2*)&C[(size_t)r * N + n] = make_float2(v0, v1);
                } else {
                    int b   = r >> 11;            // / SEQ
                    int tk  = r & (SEQ - 1);
                    int sec = n >> 10;
                    int c   = n & 1023;
                    int h   = c >> 6;
                    int d   = c & 63;
                    int bh_ = b * NHEAD + h;
                    if (sec == 0) {
                        // Q: split hi/lo (exact operand for S)
                        uint32_t hp, lp;
                        splitpackh(v0, v1, hp, lp);
                        size_t i2 = (((size_t)bh_ * SEQ + tk) * HDIM + d) >> 1;
                        ((uint32_t*)g_qh)[i2] = hp;
                        ((uint32_t*)g_ql)[i2] = lp;
                    } else if (sec == 1) {
                        // K: single fp16
                        size_t i2 = (((size_t)bh_ * SEQ + tk) * HDIM + d) >> 1;
                        ((uint32_t*)g_k)[i2] = packh(v0, v1);
                    } else {
                        // V: single fp16, transposed [B,H,D,T]
                        size_t i0 = ((size_t)bh_ * HDIM + d) * SEQ + tk;
                        g_vt[i0]       = __float2half_rn(v0);
                        g_vt[i0 + SEQ] = __float2half_rn(v1);
                    }
                }
            }
        }
    }
}

// ---------------------------------------------------------------------------
// Causal flash attention, 2-pass fp16 mma.sync. Br=128, Bc=64, D=64.
// 256 threads = 8 warps; warp w owns q rows [16w, 16w+16).
// Q fragments from gmem (L2-resident), pre-scaled by 0.125, exact hi/lo.
// K/V fragments via ldmatrix.x4. P built register-direct (exact hi/lo).
// 2-stage cp.async prefetch. LPT scheduling. grid: (SEQ/128, B*H)
// ---------------------------------------------------------------------------
#define AST 36                                   // smem row stride in u32
#define ATT_STG_U32 (2 * 64 * AST)               // Ks, Vt per stage
#define ATT_SMEM (2 * ATT_STG_U32 * 4)           // 36864 bytes

__global__ void __launch_bounds__(256, 2)
attn_h2()
{
    extern __shared__ uint32_t smu[];
    const uint32_t smb = (uint32_t)__cvta_generic_to_shared(smu);
    uint32_t* Stg = smu;                    // 2 stages of {Ks, Vt}

    const int tid  = threadIdx.x;
    const int lane = tid & 31;
    const int w    = tid >> 5;
    const int gr   = lane >> 2;
    const int tig  = lane & 3;
    const int m0   = w * 16;

    // ldmatrix lane mapping for B-operand pairs (K and V tiles)
    const int lrowB = ((lane >> 4) & 1) * 8 + (lane & 7);
    const int lcolB = ((lane >> 3) & 1) * 4;

    const int qb = gridDim.x - 1 - blockIdx.x;   // longest-processing-time first
    const int bh = blockIdx.y;
    const int b  = bh >> 4;
    const int h  = bh & 15;
    const int q0 = qb * 128;

    const size_t bhoff = (size_t)bh * SEQ * HDIM;
    const size_t vtoff = (size_t)bh * HDIM * SEQ;

    // K/V prefetch (cp.async, 2 stages)
    auto loadKV = [&](int s, int kt) {
        const int k0 = kt * 64;
        uint32_t* st = Stg + s * ATT_STG_U32;
        for (int i = tid; i < 64 * 8; i += 256) {
            int row = i >> 3, ch = i & 7;
            uint32_t* d = st + row * AST + ch * 4;
            size_t gk = bhoff + (size_t)(k0 + row) * HDIM + ch * 8;
            size_t gv = vtoff + (size_t)row * SEQ + k0 + ch * 8;
            cpasync16(d,            g_k  + gk);
            cpasync16(d + 64 * AST, g_vt + gv);
        }
    };

    const int ktmax = 2 * qb + 1;          // >= 1 always
    loadKV(0, 0); CP_COMMIT();
    loadKV(1, 1); CP_COMMIT();

    // ---- Q fragments straight from gmem, pre-scaled by 0.125 (exact in fp16)
    uint32_t qfh[4][4], qfl[4][4];
    {
        const __half2 c2 = __floats2half2_rn(0.125f, 0.125f);
        const uint32_t* qhg = (const uint32_t*)(g_qh + bhoff + (size_t)q0 * HDIM);
        const uint32_t* qlg = (const uint32_t*)(g_ql + bhoff + (size_t)q0 * HDIM);
        const int r0i = (m0 + gr) * 32;          // u32 row stride = HDIM/2
        const int r1i = (m0 + gr + 8) * 32;
#pragma unroll
        for (int dk = 0; dk < 4; dk++) {
            uint32_t t0 = qhg[r0i + dk * 8 + tig];
            uint32_t t1 = qhg[r1i + dk * 8 + tig];
            uint32_t t2 = qhg[r0i + dk * 8 + tig + 4];
            uint32_t t3 = qhg[r1i + dk * 8 + tig + 4];
            __half2 s0 = __hmul2(*(__half2*)&t0, c2);
            __half2 s1 = __hmul2(*(__half2*)&t1, c2);
            __half2 s2 = __hmul2(*(__half2*)&t2, c2);
            __half2 s3 = __hmul2(*(__half2*)&t3, c2);
            qfh[dk][0] = *(uint32_t*)&s0;
            qfh[dk][1] = *(uint32_t*)&s1;
            qfh[dk][2] = *(uint32_t*)&s2;
            qfh[dk][3] = *(uint32_t*)&s3;
            t0 = qlg[r0i + dk * 8 + tig];
            t1 = qlg[r1i + dk * 8 + tig];
            t2 = qlg[r0i + dk * 8 + tig + 4];
            t3 = qlg[r1i + dk * 8 + tig + 4];
            s0 = __hmul2(*(__half2*)&t0, c2);
            s1 = __hmul2(*(__half2*)&t1, c2);
            s2 = __hmul2(*(__half2*)&t2, c2);
            s3 = __hmul2(*(__half2*)&t3, c2);
            qfl[dk][0] = *(uint32_t*)&s0;
            qfl[dk][1] = *(uint32_t*)&s1;
            qfl[dk][2] = *(uint32_t*)&s2;
            qfl[dk][3] = *(uint32_t*)&s3;
        }
    }

    float o[8][4];
#pragma unroll
    for (int nt = 0; nt < 8; nt++)
#pragma unroll
        for (int e = 0; e < 4; e++) o[nt][e] = 0.f;
    float mrow[2] = {-1e30f, -1e30f};
    float lrow[2] = {0.f, 0.f};

    for (int kt = 0; kt <= ktmax; kt++) {
        const int s = kt & 1;
        if (kt == ktmax) { CP_WAIT0(); } else { CP_WAIT1(); }
        __syncthreads();

        const uint32_t ksb = smb + (uint32_t)s * ATT_STG_U32 * 4;
        const uint32_t vtb = ksb + 64 * AST * 4;
        const int k0 = kt * 64;

        // ---- S = Q K^T (2-pass), K fragments via ldmatrix
        float sfr[8][4];
#pragma unroll
        for (int nt = 0; nt < 8; nt++)
#pragma unroll
            for (int e = 0; e < 4; e++) sfr[nt][e] = 0.f;

#pragma unroll
        for (int dk = 0; dk < 4; dk++) {
            uint32_t kf[8][2];
#pragma unroll
            for (int j = 0; j < 4; j++) {
                uint32_t koff = ((j * 16 + lrowB) * AST + dk * 8 + lcolB) * 4;
                ldsm_x4(kf[2 * j][0], kf[2 * j][1], kf[2 * j + 1][0], kf[2 * j + 1][1],
                        ksb + koff);
            }
#pragma unroll
            for (int nt = 0; nt < 8; nt++)
                mma_f16(sfr[nt], qfh[dk], kf[nt]);
#pragma unroll
            for (int nt = 0; nt < 8; nt++)
                mma_f16(sfr[nt], qfl[dk], kf[nt]);
        }

        // ---- causal mask (only near the diagonal)
        if (k0 + 63 > q0 + m0) {
#pragma unroll
            for (int nt = 0; nt < 8; nt++)
#pragma unroll
                for (int e = 0; e < 4; e++) {
                    int rg = q0 + m0 + gr + (e >> 1) * 8;
                    int cg = k0 + nt * 8 + 2 * tig + (e & 1);
                    if (cg > rg) sfr[nt][e] = -1e30f;
                }
        }

        // ---- online softmax (thread rows: gr, gr+8); p kept in sfr
        float mx0 = -1e30f, mx1 = -1e30f;
#pragma unroll
        for (int nt = 0; nt < 8; nt++) {
            mx0 = fmaxf(mx0, fmaxf(sfr[nt][0], sfr[nt][1]));
            mx1 = fmaxf(mx1, fmaxf(sfr[nt][2], sfr[nt][3]));
        }
        mx0 = fmaxf(mx0, __shfl_xor_sync(0xffffffffu, mx0, 1));
        mx0 = fmaxf(mx0, __shfl_xor_sync(0xffffffffu, mx0, 2));
        mx1 = fmaxf(mx1, __shfl_xor_sync(0xffffffffu, mx1, 1));
        mx1 = fmaxf(mx1, __shfl_xor_sync(0xffffffffu, mx1, 2));

        float nm0 = fmaxf(mrow[0], mx0);
        float nm1 = fmaxf(mrow[1], mx1);
        float f0  = __expf(mrow[0] - nm0);
        float f1  = __expf(mrow[1] - nm1);

        float ps0 = 0.f, ps1 = 0.f;
#pragma unroll
        for (int nt = 0; nt < 8; nt++) {
            sfr[nt][0] = __expf(sfr[nt][0] - nm0);
            sfr[nt][1] = __expf(sfr[nt][1] - nm0);
            sfr[nt][2] = __expf(sfr[nt][2] - nm1);
            sfr[nt][3] = __expf(sfr[nt][3] - nm1);
            ps0 += sfr[nt][0] + sfr[nt][1];
            ps1 += sfr[nt][2] + sfr[nt][3];
        }
        ps0 += __shfl_xor_sync(0xffffffffu, ps0, 1);
        ps0 += __shfl_xor_sync(0xffffffffu, ps0, 2);
        ps1 += __shfl_xor_sync(0xffffffffu, ps1, 1);
        ps1 += __shfl_xor_sync(0xffffffffu, ps1, 2);

        lrow[0] = lrow[0] * f0 + ps0;
        lrow[1] = lrow[1] * f1 + ps1;
        mrow[0] = nm0;
        mrow[1] = nm1;
#pragma unroll
        for (int nt = 0; nt < 8; nt++) {
            o[nt][0] *= f0; o[nt][1] *= f0;
            o[nt][2] *= f1; o[nt][3] *= f1;
        }

        // ---- O += P V (2-pass), P register-direct, V via ldmatrix
#pragma unroll
        for (int kk = 0; kk < 4; kk++) {
            uint32_t pfh[4], pfl[4];
            splitpackh(sfr[2 * kk    ][0], sfr[2 * kk    ][1], pfh[0], pfl[0]);
            splitpackh(sfr[2 * kk    ][2], sfr[2 * kk    ][3], pfh[1], pfl[1]);
            splitpackh(sfr[2 * kk + 1][0], sfr[2 * kk + 1][1], pfh[2], pfl[2]);
            splitpackh(sfr[2 * kk + 1][2], sfr[2 * kk + 1][3], pfh[3], pfl[3]);
            uint32_t vf[8][2];
#pragma unroll
            for (int j = 0; j < 4; j++) {
                uint32_t voff = ((j * 16 + lrowB) * AST + kk * 8 + lcolB) * 4;
                ldsm_x4(vf[2 * j][0], vf[2 * j][1], vf[2 * j + 1][0], vf[2 * j + 1][1],
                        vtb + voff);
            }
#pragma unroll
            for (int nt = 0; nt < 8; nt++)
                mma_f16(o[nt], pfh, vf[nt]);
#pragma unroll
            for (int nt = 0; nt < 8; nt++)
                mma_f16(o[nt], pfl, vf[nt]);
        }
        __syncthreads();     // all warps done with stage s
        if (kt + 2 <= ktmax) { loadKV(s, kt + 2); CP_COMMIT(); }
    }

    // ---- normalize and store to g_ao (single fp16, [B*T, C])
    float inv0 = 1.0f / lrow[0];
    float inv1 = 1.0f / lrow[1];
    int r0 = q0 + m0 + gr;
    uint32_t* ao = (uint32_t*)g_ao;
#pragma unroll
    for (int nt = 0; nt < 8; nt++) {
        size_t cu = (size_t)h * 32 + nt * 4 + tig;   // u32 col
        ao[(size_t)(b * SEQ + r0) * (EMBED / 2) + cu] =
            packh(o[nt][0] * inv0, o[nt][1] * inv0);
        ao[(size_t)(b * SEQ + r0 + 8) * (EMBED / 2) + cu] =
            packh(o[nt][2] * inv1, o[nt][3] * inv1);
    }
}

// ---------------------------------------------------------------------------
extern "C" void kernel_launch(void* const* d_in, const int* in_sizes, int n_in,
                              void* d_out, int out_size)
{
    const float* x      = (const float*)d_in[0];   // [4,2048,1024]
    const float* W_qkv  = (const float*)d_in[1];   // [3072,1024]
    const float* W_proj = (const float*)d_in[2];   // [1024,1024]
    float* out = (float*)d_out;                    // [4,2048,1024]

    __half *xp, *wq, *wp, *ao;
    cudaGetSymbolAddress((void**)&xp, g_x);
    cudaGetSymbolAddress((void**)&wq, g_wq);
    cudaGetSymbolAddress((void**)&wp, g_wp);
    cudaGetSymbolAddress((void**)&ao, g_ao);

    // 0) prep: everything to single fp16
    {
        int n1 = MROWS * EMBED / 4, n2 = 3 * EMBED * EMBED / 4, n3 = EMBED * EMBED / 4;
        cvt_f32h<<<(n1 + 255) / 256, 256>>>((const float4*)x, (uint2*)xp, n1);
        cvt_f32h<<<(n2 + 255) / 256, 256>>>((const float4*)W_qkv, (uint2*)wq, n2);
        cvt_f32h<<<(n3 + 255) / 256, 256>>>((const float4*)W_proj, (uint2*)wp, n3);
    }

    // 1) QKV projection (single-pass fp16) with scatter epilogue
    {
        cudaFuncSetAttribute((const void*)gemm_h1<1>,
                             cudaFuncAttributeMaxDynamicSharedMemorySize, GEMM_SMEM);
        dim3 grid(3 * EMBED / 128, MROWS / 128);
        gemm_h1<1><<<grid, 256, GEMM_SMEM>>>(xp, wq, nullptr, EMBED, 3 * EMBED);
    }

    // 2) causal flash attention -> g_ao (single fp16)
    {
        cudaFuncSetAttribute((const void*)attn_h2,
                             cudaFuncAttributeMaxDynamicSharedMemorySize, ATT_SMEM);
        dim3 grid(SEQ / 128, BATCH * NHEAD);
        attn_h2<<<grid, 256, ATT_SMEM>>>();
    }

    // 3) output projection (single-pass fp16) -> d_out (fp32)
    {
        cudaFuncSetAttribute((const void*)gemm_h1<0>,
                             cudaFuncAttributeMaxDynamicSharedMemorySize, GEMM_SMEM);
        dim3 grid(EMBED / 128, MROWS / 128);
        gemm_h1<0><<<grid, 256, GEMM_SMEM>>>(ao, wp, out, EMBED, EMBED);
    }
}

// round 14
// speedup vs baseline: 2.6004x; 1.2530x over previous
#include <cuda_runtime.h>
#include <cuda_fp16.h>
#include <cstdint>

// Problem constants
#define EMBED   1024
#define NHEAD   16
#define HDIM    64
#define BATCH   4
#define SEQ     2048
#define MROWS   (BATCH * SEQ)                 // 8192
#define QKVN    (BATCH * NHEAD * SEQ * HDIM)  // 8388608

// ---------------------------------------------------------------------------
// Persistent scratch (all single fp16)
// ---------------------------------------------------------------------------
__device__ __align__(16) __half g_x  [MROWS * EMBED];
__device__ __align__(16) __half g_wq [3 * EMBED * EMBED];
__device__ __align__(16) __half g_wp [EMBED * EMBED];
__device__ __align__(16) __half g_q  [QKVN];   // [B,H,T,D]
__device__ __align__(16) __half g_k  [QKVN];   // [B,H,T,D]
__device__ __align__(16) __half g_vt [QKVN];   // [B,H,D,T] (transposed)
__device__ __align__(16) __half g_ao [MROWS * EMBED];   // [B*T, C]

// ---------------------------------------------------------------------------
// helpers
// ---------------------------------------------------------------------------
__device__ __forceinline__ void mma_f16(float* c, const uint32_t* a, const uint32_t* b) {
    asm volatile(
        "mma.sync.aligned.m16n8k16.row.col.f32.f16.f16.f32 "
        "{%0,%1,%2,%3}, {%4,%5,%6,%7}, {%8,%9}, {%0,%1,%2,%3};"
        : "+f"(c[0]), "+f"(c[1]), "+f"(c[2]), "+f"(c[3])
        : "r"(a[0]), "r"(a[1]), "r"(a[2]), "r"(a[3]), "r"(b[0]), "r"(b[1]));
}
__device__ __forceinline__ void ldsm_x4(uint32_t& r0, uint32_t& r1,
                                        uint32_t& r2, uint32_t& r3, uint32_t addr) {
    asm volatile("ldmatrix.sync.aligned.m8n8.x4.shared.b16 {%0,%1,%2,%3}, [%4];"
        : "=r"(r0), "=r"(r1), "=r"(r2), "=r"(r3) : "r"(addr));
}
__device__ __forceinline__ uint32_t packh(float x0, float x1) {
    __half2 h = __floats2half2_rn(x0, x1);
    return *(uint32_t*)&h;
}
__device__ __forceinline__ void cpasync16(void* s, const void* g) {
    uint32_t sa = (uint32_t)__cvta_generic_to_shared(s);
    asm volatile("cp.async.cg.shared.global [%0], [%1], 16;\n" :: "r"(sa), "l"(g));
}
#define CP_COMMIT() asm volatile("cp.async.commit_group;\n" ::: "memory")
#define CP_WAIT1()  asm volatile("cp.async.wait_group 1;\n"  ::: "memory")
#define CP_WAIT0()  asm volatile("cp.async.wait_group 0;\n"  ::: "memory")

// ---------------------------------------------------------------------------
// prep kernel: fp32 -> fp16
// ---------------------------------------------------------------------------
__global__ void cvt_f32h(const float4* __restrict__ src,
                         uint2* __restrict__ dst, int n4)
{
    int i = blockIdx.x * blockDim.x + threadIdx.x;
    if (i < n4) {
        float4 v = src[i];
        dst[i] = make_uint2(packh(v.x, v.y), packh(v.z, v.w));
    }
}

// ---------------------------------------------------------------------------
// single-pass fp16 GEMM:  C = A @ B^T.  A:[M,K] rm fp16, B:[N,K] rm fp16.
// Block 128x128, kTile 32 (fp16), 256 threads (8 warps, warp tile 32x64).
// 2-stage cp.async pipeline, fragments via ldmatrix.x4 (conflict-free).
// MODE 0: fp32 store C.  MODE 1: QKV scatter epilogue.
// ---------------------------------------------------------------------------
#define GST    20                          // smem row stride in u32 (16 data + 4 pad)
#define GCOMP  (128 * GST)                 // u32 per component per stage
#define GSTAGE (2 * GCOMP)                 // A, B
#define GEMM_SMEM (2 * GSTAGE * 4)         // 40960 bytes

template <int MODE>
__global__ void __launch_bounds__(256, 2)
gemm_h1(const __half* __restrict__ A, const __half* __restrict__ B,
        float* __restrict__ C, int K, int N)
{
    extern __shared__ uint32_t smu[];
    const uint32_t smb = (uint32_t)__cvta_generic_to_shared(smu);

    const int tid  = threadIdx.x;
    const int lane = tid & 31;
    const int w    = tid >> 5;
    const int gr   = lane >> 2;
    const int tig  = lane & 3;
    const int wm   = w & 3;              // 32-row quadrant
    const int wn   = w >> 2;             // 64-col half

    // ldmatrix lane mappings
    const int lrowA = (lane & 7) + ((lane >> 3) & 1) * 8;
    const int lcolA = (lane >> 4) * 4;
    const int lrowB = ((lane >> 4) & 1) * 8 + (lane & 7);
    const int lcolB = ((lane >> 3) & 1) * 4;

    const int row0 = blockIdx.y * 128;
    const int col0 = blockIdx.x * 128;

    float acc[2][8][4];
#pragma unroll
    for (int i = 0; i < 2; i++)
#pragma unroll
        for (int j = 0; j < 8; j++)
#pragma unroll
            for (int e = 0; e < 4; e++) acc[i][j][e] = 0.f;

    // stage loader: per component 128 rows x 32 fp16 (4 x 16B chunks per row)
    auto loadTile = [&](int s, int kt) {
        uint32_t* st = smu + (size_t)s * GSTAGE;
#pragma unroll
        for (int p = 0; p < 2; p++) {
            int c   = tid + 256 * p;         // 0..511
            int row = c >> 2;
            int ch  = c & 3;
            uint32_t* d0 = st + row * GST + ch * 4;
            size_t ga = (size_t)(row0 + row) * K + kt + ch * 8;
            size_t gb = (size_t)(col0 + row) * K + kt + ch * 8;
            cpasync16(d0,         A + ga);
            cpasync16(d0 + GCOMP, B + gb);
        }
    };

    const int nk = K / 32;
    loadTile(0, 0);  CP_COMMIT();
    loadTile(1, 32); CP_COMMIT();

    for (int t = 0; t < nk; t++) {
        const int s = t & 1;
        if (t >= nk - 2) { CP_WAIT0(); } else { CP_WAIT1(); }
        __syncthreads();

        const uint32_t stb = smb + (uint32_t)s * GSTAGE * 4;

#pragma unroll
        for (int ks = 0; ks < 2; ks++) {
            const int base = ks * 8;
            uint32_t af[2][4];
#pragma unroll
            for (int mt = 0; mt < 2; mt++) {
                uint32_t aoff = ((wm * 32 + mt * 16 + lrowA) * GST + base + lcolA) * 4;
                ldsm_x4(af[mt][0], af[mt][1], af[mt][2], af[mt][3], stb + aoff);
            }
            uint32_t bf[8][2];
#pragma unroll
            for (int j = 0; j < 4; j++) {
                uint32_t boff = ((wn * 64 + j * 16 + lrowB) * GST + base + lcolB) * 4;
                ldsm_x4(bf[2 * j][0], bf[2 * j][1], bf[2 * j + 1][0], bf[2 * j + 1][1],
                        stb + GCOMP * 4 + boff);
            }
#pragma unroll
            for (int mt = 0; mt < 2; mt++)
#pragma unroll
                for (int nt = 0; nt < 8; nt++)
                    mma_f16(acc[mt][nt], af[mt], bf[nt]);
        }
        __syncthreads();
        if (t + 2 < nk) { loadTile(s, (t + 2) * 32); CP_COMMIT(); }
    }

    // ---- epilogue
#pragma unroll
    for (int mt = 0; mt < 2; mt++) {
#pragma unroll
        for (int e2 = 0; e2 < 2; e2++) {
            int r = row0 + wm * 32 + mt * 16 + gr + e2 * 8;
#pragma unroll
            for (int nt = 0; nt < 8; nt++) {
                int n = col0 + wn * 64 + nt * 8 + 2 * tig;
                float v0 = acc[mt][nt][e2 * 2 + 0];
                float v1 = acc[mt][nt][e2 * 2 + 1];
                if (MODE == 0) {
                    *(float2*)&C[(size_t)r * N + n] = make_float2(v0, v1);
                } else {
                    int b   = r >> 11;            // / SEQ
                    int tk  = r & (SEQ - 1);
                    int sec = n >> 10;
                    int c   = n & 1023;
                    int h   = c >> 6;
                    int d   = c & 63;
                    int bh_ = b * NHEAD + h;
                    if (sec == 2) {
                        // V: single fp16, transposed [B,H,D,T]
                        size_t i0 = ((size_t)bh_ * HDIM + d) * SEQ + tk;
                        g_vt[i0]       = __float2half_rn(v0);
                        g_vt[i0 + SEQ] = __float2half_rn(v1);
                    } else {
                        // Q or K: single fp16, [B,H,T,D]
                        size_t i2 = (((size_t)bh_ * SEQ + tk) * HDIM + d) >> 1;
                        uint32_t* dst = (sec == 0) ? (uint32_t*)g_q : (uint32_t*)g_k;
                        dst[i2] = packh(v0, v1);
                    }
                }
            }
        }
    }
}

// ---------------------------------------------------------------------------
// Causal flash attention, single-pass fp16 mma.sync. Br=128, Bc=64, D=64.
// 256 threads = 8 warps; warp w owns q rows [16w, 16w+16).
// Q fragments from gmem (L2-resident), pre-scaled by 0.125.
// K/V fragments via ldmatrix.x4. P packed register-direct from S fragments.
// 2-stage cp.async prefetch. LPT scheduling. grid: (SEQ/128, B*H)
// ---------------------------------------------------------------------------
#define AST 36                                   // smem row stride in u32
#define ATT_STG_U32 (2 * 64 * AST)               // Ks, Vt per stage
#define ATT_SMEM (2 * ATT_STG_U32 * 4)           // 36864 bytes

__global__ void __launch_bounds__(256, 2)
attn_h1()
{
    extern __shared__ uint32_t smu[];
    const uint32_t smb = (uint32_t)__cvta_generic_to_shared(smu);
    uint32_t* Stg = smu;                    // 2 stages of {Ks, Vt}

    const int tid  = threadIdx.x;
    const int lane = tid & 31;
    const int w    = tid >> 5;
    const int gr   = lane >> 2;
    const int tig  = lane & 3;
    const int m0   = w * 16;

    // ldmatrix lane mapping for B-operand pairs (K and V tiles)
    const int lrowB = ((lane >> 4) & 1) * 8 + (lane & 7);
    const int lcolB = ((lane >> 3) & 1) * 4;

    const int qb = gridDim.x - 1 - blockIdx.x;   // longest-processing-time first
    const int bh = blockIdx.y;
    const int b  = bh >> 4;
    const int h  = bh & 15;
    const int q0 = qb * 128;

    const size_t bhoff = (size_t)bh * SEQ * HDIM;
    const size_t vtoff = (size_t)bh * HDIM * SEQ;

    // K/V prefetch (cp.async, 2 stages)
    auto loadKV = [&](int s, int kt) {
        const int k0 = kt * 64;
        uint32_t* st = Stg + s * ATT_STG_U32;
        for (int i = tid; i < 64 * 8; i += 256) {
            int row = i >> 3, ch = i & 7;
            uint32_t* d = st + row * AST + ch * 4;
            size_t gk = bhoff + (size_t)(k0 + row) * HDIM + ch * 8;
            size_t gv = vtoff + (size_t)row * SEQ + k0 + ch * 8;
            cpasync16(d,            g_k  + gk);
            cpasync16(d + 64 * AST, g_vt + gv);
        }
    };

    const int ktmax = 2 * qb + 1;          // >= 1 always
    loadKV(0, 0); CP_COMMIT();
    loadKV(1, 1); CP_COMMIT();

    // ---- Q fragments straight from gmem, pre-scaled by 0.125 (exact in fp16)
    uint32_t qf[4][4];
    {
        const __half2 c2 = __floats2half2_rn(0.125f, 0.125f);
        const uint32_t* qg = (const uint32_t*)(g_q + bhoff + (size_t)q0 * HDIM);
        const int r0i = (m0 + gr) * 32;          // u32 row stride = HDIM/2
        const int r1i = (m0 + gr + 8) * 32;
#pragma unroll
        for (int dk = 0; dk < 4; dk++) {
            uint32_t t0 = qg[r0i + dk * 8 + tig];
            uint32_t t1 = qg[r1i + dk * 8 + tig];
            uint32_t t2 = qg[r0i + dk * 8 + tig + 4];
            uint32_t t3 = qg[r1i + dk * 8 + tig + 4];
            __half2 s0 = __hmul2(*(__half2*)&t0, c2);
            __half2 s1 = __hmul2(*(__half2*)&t1, c2);
            __half2 s2 = __hmul2(*(__half2*)&t2, c2);
            __half2 s3 = __hmul2(*(__half2*)&t3, c2);
            qf[dk][0] = *(uint32_t*)&s0;
            qf[dk][1] = *(uint32_t*)&s1;
            qf[dk][2] = *(uint32_t*)&s2;
            qf[dk][3] = *(uint32_t*)&s3;
        }
    }

    float o[8][4];
#pragma unroll
    for (int nt = 0; nt < 8; nt++)
#pragma unroll
        for (int e = 0; e < 4; e++) o[nt][e] = 0.f;
    float mrow[2] = {-1e30f, -1e30f};
    float lrow[2] = {0.f, 0.f};

    for (int kt = 0; kt <= ktmax; kt++) {
        const int s = kt & 1;
        if (kt == ktmax) { CP_WAIT0(); } else { CP_WAIT1(); }
        __syncthreads();

        const uint32_t ksb = smb + (uint32_t)s * ATT_STG_U32 * 4;
        const uint32_t vtb = ksb + 64 * AST * 4;
        const int k0 = kt * 64;

        // ---- S = Q K^T (single pass), K fragments via ldmatrix
        float sfr[8][4];
#pragma unroll
        for (int nt = 0; nt < 8; nt++)
#pragma unroll
            for (int e = 0; e < 4; e++) sfr[nt][e] = 0.f;

#pragma unroll
        for (int dk = 0; dk < 4; dk++) {
            uint32_t kf[8][2];
#pragma unroll
            for (int j = 0; j < 4; j++) {
                uint32_t koff = ((j * 16 + lrowB) * AST + dk * 8 + lcolB) * 4;
                ldsm_x4(kf[2 * j][0], kf[2 * j][1], kf[2 * j + 1][0], kf[2 * j + 1][1],
                        ksb + koff);
            }
#pragma unroll
            for (int nt = 0; nt < 8; nt++)
                mma_f16(sfr[nt], qf[dk], kf[nt]);
        }

        // ---- causal mask (only near the diagonal)
        if (k0 + 63 > q0 + m0) {
#pragma unroll
            for (int nt = 0; nt < 8; nt++)
#pragma unroll
                for (int e = 0; e < 4; e++) {
                    int rg = q0 + m0 + gr + (e >> 1) * 8;
                    int cg = k0 + nt * 8 + 2 * tig + (e & 1);
                    if (cg > rg) sfr[nt][e] = -1e30f;
                }
        }

        // ---- online softmax (thread rows: gr, gr+8); p kept in sfr
        float mx0 = -1e30f, mx1 = -1e30f;
#pragma unroll
        for (int nt = 0; nt < 8; nt++) {
            mx0 = fmaxf(mx0, fmaxf(sfr[nt][0], sfr[nt][1]));
            mx1 = fmaxf(mx1, fmaxf(sfr[nt][2], sfr[nt][3]));
        }
        mx0 = fmaxf(mx0, __shfl_xor_sync(0xffffffffu, mx0, 1));
        mx0 = fmaxf(mx0, __shfl_xor_sync(0xffffffffu, mx0, 2));
        mx1 = fmaxf(mx1, __shfl_xor_sync(0xffffffffu, mx1, 1));
        mx1 = fmaxf(mx1, __shfl_xor_sync(0xffffffffu, mx1, 2));

        float nm0 = fmaxf(mrow[0], mx0);
        float nm1 = fmaxf(mrow[1], mx1);
        float f0  = __expf(mrow[0] - nm0);
        float f1  = __expf(mrow[1] - nm1);

        float ps0 = 0.f, ps1 = 0.f;
#pragma unroll
        for (int nt = 0; nt < 8; nt++) {
            sfr[nt][0] = __expf(sfr[nt][0] - nm0);
            sfr[nt][1] = __expf(sfr[nt][1] - nm0);
            sfr[nt][2] = __expf(sfr[nt][2] - nm1);
            sfr[nt][3] = __expf(sfr[nt][3] - nm1);
            ps0 += sfr[nt][0] + sfr[nt][1];
            ps1 += sfr[nt][2] + sfr[nt][3];
        }
        ps0 += __shfl_xor_sync(0xffffffffu, ps0, 1);
        ps0 += __shfl_xor_sync(0xffffffffu, ps0, 2);
        ps1 += __shfl_xor_sync(0xffffffffu, ps1, 1);
        ps1 += __shfl_xor_sync(0xffffffffu, ps1, 2);

        lrow[0] = lrow[0] * f0 + ps0;
        lrow[1] = lrow[1] * f1 + ps1;
        mrow[0] = nm0;
        mrow[1] = nm1;
#pragma unroll
        for (int nt = 0; nt < 8; nt++) {
            o[nt][0] *= f0; o[nt][1] *= f0;
            o[nt][2] *= f1; o[nt][3] *= f1;
        }

        // ---- O += P V (single pass), P packed register-direct, V via ldmatrix
#pragma unroll
        for (int kk = 0; kk < 4; kk++) {
            uint32_t pf[4];
            pf[0] = packh(sfr[2 * kk    ][0], sfr[2 * kk    ][1]);
            pf[1] = packh(sfr[2 * kk    ][2], sfr[2 * kk    ][3]);
            pf[2] = packh(sfr[2 * kk + 1][0], sfr[2 * kk + 1][1]);
            pf[3] = packh(sfr[2 * kk + 1][2], sfr[2 * kk + 1][3]);
            uint32_t vf[8][2];
#pragma unroll
            for (int j = 0; j < 4; j++) {
                uint32_t voff = ((j * 16 + lrowB) * AST + kk * 8 + lcolB) * 4;
                ldsm_x4(vf[2 * j][0], vf[2 * j][1], vf[2 * j + 1][0], vf[2 * j + 1][1],
                        vtb + voff);
            }
#pragma unroll
            for (int nt = 0; nt < 8; nt++)
                mma_f16(o[nt], pf, vf[nt]);
        }
        __syncthreads();     // all warps done with stage s
        if (kt + 2 <= ktmax) { loadKV(s, kt + 2); CP_COMMIT(); }
    }

    // ---- normalize and store to g_ao (single fp16, [B*T, C])
    float inv0 = 1.0f / lrow[0];
    float inv1 = 1.0f / lrow[1];
    int r0 = q0 + m0 + gr;
    uint32_t* ao = (uint32_t*)g_ao;
#pragma unroll
    for (int nt = 0; nt < 8; nt++) {
        size_t cu = (size_t)h * 32 + nt * 4 + tig;   // u32 col
        ao[(size_t)(b * SEQ + r0) * (EMBED / 2) + cu] =
            packh(o[nt][0] * inv0, o[nt][1] * inv0);
        ao[(size_t)(b * SEQ + r0 + 8) * (EMBED / 2) + cu] =
            packh(o[nt][2] * inv1, o[nt][3] * inv1);
    }
}

// ---------------------------------------------------------------------------
extern "C" void kernel_launch(void* const* d_in, const int* in_sizes, int n_in,
                              void* d_out, int out_size)
{
    const float* x      = (const float*)d_in[0];   // [4,2048,1024]
    const float* W_qkv  = (const float*)d_in[1];   // [3072,1024]
    const float* W_proj = (const float*)d_in[2];   // [1024,1024]
    float* out = (float*)d_out;                    // [4,2048,1024]

    __half *xp, *wq, *wp, *ao;
    cudaGetSymbolAddress((void**)&xp, g_x);
    cudaGetSymbolAddress((void**)&wq, g_wq);
    cudaGetSymbolAddress((void**)&wp, g_wp);
    cudaGetSymbolAddress((void**)&ao, g_ao);

    // 0) prep: everything to single fp16
    {
        int n1 = MROWS * EMBED / 4, n2 = 3 * EMBED * EMBED / 4, n3 = EMBED * EMBED / 4;
        cvt_f32h<<<(n1 + 255) / 256, 256>>>((const float4*)x, (uint2*)xp, n1);
        cvt_f32h<<<(n2 + 255) / 256, 256>>>((const float4*)W_qkv, (uint2*)wq, n2);
        cvt_f32h<<<(n3 + 255) / 256, 256>>>((const float4*)W_proj, (uint2*)wp, n3);
    }

    // 1) QKV projection (single-pass fp16) with scatter epilogue
    {
        cudaFuncSetAttribute((const void*)gemm_h1<1>,
                             cudaFuncAttributeMaxDynamicSharedMemorySize, GEMM_SMEM);
        dim3 grid(3 * EMBED / 128, MROWS / 128);
        gemm_h1<1><<<grid, 256, GEMM_SMEM>>>(xp, wq, nullptr, EMBED, 3 * EMBED);
    }

    // 2) causal flash attention -> g_ao (single fp16)
    {
        cudaFuncSetAttribute((const void*)attn_h1,
                             cudaFuncAttributeMaxDynamicSharedMemorySize, ATT_SMEM);
        dim3 grid(SEQ / 128, BATCH * NHEAD);
        attn_h1<<<grid, 256, ATT_SMEM>>>();
    }

    // 3) output projection (single-pass fp16) -> d_out (fp32)
    {
        cudaFuncSetAttribute((const void*)gemm_h1<0>,
                             cudaFuncAttributeMaxDynamicSharedMemorySize, GEMM_SMEM);
        dim3 grid(EMBED / 128, MROWS / 128);
        gemm_h1<0><<<grid, 256, GEMM_SMEM>>>(ao, wp, out, EMBED, EMBED);
    }
}

// round 15
// speedup vs baseline: 2.6480x; 1.0183x over previous
#include <cuda_runtime.h>
#include <cuda_fp16.h>
#include <cstdint>

// Problem constants
#define EMBED   1024
#define NHEAD   16
#define HDIM    64
#define BATCH   4
#define SEQ     2048
#define MROWS   (BATCH * SEQ)                 // 8192
#define QKVN    (BATCH * NHEAD * SEQ * HDIM)  // 8388608

// ---------------------------------------------------------------------------
// Persistent scratch (all single fp16)
// ---------------------------------------------------------------------------
__device__ __align__(16) __half g_x  [MROWS * EMBED];
__device__ __align__(16) __half g_wq [3 * EMBED * EMBED];
__device__ __align__(16) __half g_wp [EMBED * EMBED];
__device__ __align__(16) __half g_q  [QKVN];   // [B,H,T,D], pre-scaled by 0.125
__device__ __align__(16) __half g_k  [QKVN];   // [B,H,T,D]
__device__ __align__(16) __half g_vt [QKVN];   // [B,H,D,T] (transposed)
__device__ __align__(16) __half g_ao [MROWS * EMBED];   // [B*T, C]

// ---------------------------------------------------------------------------
// helpers
// ---------------------------------------------------------------------------
__device__ __forceinline__ void mma_f16(float* c, const uint32_t* a, const uint32_t* b) {
    asm volatile(
        "mma.sync.aligned.m16n8k16.row.col.f32.f16.f16.f32 "
        "{%0,%1,%2,%3}, {%4,%5,%6,%7}, {%8,%9}, {%0,%1,%2,%3};"
        : "+f"(c[0]), "+f"(c[1]), "+f"(c[2]), "+f"(c[3])
        : "r"(a[0]), "r"(a[1]), "r"(a[2]), "r"(a[3]), "r"(b[0]), "r"(b[1]));
}
__device__ __forceinline__ void ldsm_x4(uint32_t& r0, uint32_t& r1,
                                        uint32_t& r2, uint32_t& r3, uint32_t addr) {
    asm volatile("ldmatrix.sync.aligned.m8n8.x4.shared.b16 {%0,%1,%2,%3}, [%4];"
        : "=r"(r0), "=r"(r1), "=r"(r2), "=r"(r3) : "r"(addr));
}
__device__ __forceinline__ uint32_t packh(float x0, float x1) {
    __half2 h = __floats2half2_rn(x0, x1);
    return *(uint32_t*)&h;
}
__device__ __forceinline__ void cpasync16(void* s, const void* g) {
    uint32_t sa = (uint32_t)__cvta_generic_to_shared(s);
    asm volatile("cp.async.cg.shared.global [%0], [%1], 16;\n" :: "r"(sa), "l"(g));
}
#define CP_COMMIT() asm volatile("cp.async.commit_group;\n" ::: "memory")
#define CP_WAIT1()  asm volatile("cp.async.wait_group 1;\n"  ::: "memory")
#define CP_WAIT0()  asm volatile("cp.async.wait_group 0;\n"  ::: "memory")

// ---------------------------------------------------------------------------
// prep kernel: fp32 -> fp16
// ---------------------------------------------------------------------------
__global__ void cvt_f32h(const float4* __restrict__ src,
                         uint2* __restrict__ dst, int n4)
{
    int i = blockIdx.x * blockDim.x + threadIdx.x;
    if (i < n4) {
        float4 v = src[i];
        dst[i] = make_uint2(packh(v.x, v.y), packh(v.z, v.w));
    }
}

// ---------------------------------------------------------------------------
// single-pass fp16 GEMM:  C = A @ B^T.  A:[M,K] rm fp16, B:[N,K] rm fp16.
// Block 128x128, kTile 32 (fp16), 256 threads (8 warps, warp tile 32x64).
// 3-stage cp.async ring -> ONE __syncthreads per k-iter; next load issued
// right after the barrier, ahead of compute. Fragments via ldmatrix.x4.
// MODE 0: fp32 store C.  MODE 1: QKV scatter epilogue (Q pre-scaled 0.125).
// ---------------------------------------------------------------------------
#define GST    20                          // smem row stride in u32 (16 data + 4 pad)
#define GCOMP  (128 * GST)                 // u32 per component per stage
#define GSTAGE (2 * GCOMP)                 // A, B
#define GEMM_SMEM (3 * GSTAGE * 4)         // 61440 bytes

template <int MODE>
__global__ void __launch_bounds__(256, 2)
gemm_h1(const __half* __restrict__ A, const __half* __restrict__ B,
        float* __restrict__ C, int K, int N)
{
    extern __shared__ uint32_t smu[];
    const uint32_t smb = (uint32_t)__cvta_generic_to_shared(smu);

    const int tid  = threadIdx.x;
    const int lane = tid & 31;
    const int w    = tid >> 5;
    const int gr   = lane >> 2;
    const int tig  = lane & 3;
    const int wm   = w & 3;              // 32-row quadrant
    const int wn   = w >> 2;             // 64-col half

    // ldmatrix lane mappings
    const int lrowA = (lane & 7) + ((lane >> 3) & 1) * 8;
    const int lcolA = (lane >> 4) * 4;
    const int lrowB = ((lane >> 4) & 1) * 8 + (lane & 7);
    const int lcolB = ((lane >> 3) & 1) * 4;

    const int row0 = blockIdx.y * 128;
    const int col0 = blockIdx.x * 128;

    float acc[2][8][4];
#pragma unroll
    for (int i = 0; i < 2; i++)
#pragma unroll
        for (int j = 0; j < 8; j++)
#pragma unroll
            for (int e = 0; e < 4; e++) acc[i][j][e] = 0.f;

    // stage loader: per component 128 rows x 32 fp16 (4 x 16B chunks per row)
    auto loadTile = [&](int s, int kt) {
        uint32_t* st = smu + (size_t)s * GSTAGE;
#pragma unroll
        for (int p = 0; p < 2; p++) {
            int c   = tid + 256 * p;         // 0..511
            int row = c >> 2;
            int ch  = c & 3;
            uint32_t* d0 = st + row * GST + ch * 4;
            size_t ga = (size_t)(row0 + row) * K + kt + ch * 8;
            size_t gb = (size_t)(col0 + row) * K + kt + ch * 8;
            cpasync16(d0,         A + ga);
            cpasync16(d0 + GCOMP, B + gb);
        }
    };

    const int nk = K / 32;
    loadTile(0, 0);  CP_COMMIT();
    loadTile(1, 32); CP_COMMIT();

    for (int t = 0; t < nk; t++) {
        const int s = t % 3;
        if (t < nk - 1) { CP_WAIT1(); } else { CP_WAIT0(); }
        __syncthreads();                       // single barrier per iter
        if (t + 2 < nk) { loadTile((t + 2) % 3, (t + 2) * 32); CP_COMMIT(); }

        const uint32_t stb = smb + (uint32_t)s * GSTAGE * 4;

#pragma unroll
        for (int ks = 0; ks < 2; ks++) {
            const int base = ks * 8;
            uint32_t af[2][4];
#pragma unroll
            for (int mt = 0; mt < 2; mt++) {
                uint32_t aoff = ((wm * 32 + mt * 16 + lrowA) * GST + base + lcolA) * 4;
                ldsm_x4(af[mt][0], af[mt][1], af[mt][2], af[mt][3], stb + aoff);
            }
            uint32_t bf[8][2];
#pragma unroll
            for (int j = 0; j < 4; j++) {
                uint32_t boff = ((wn * 64 + j * 16 + lrowB) * GST + base + lcolB) * 4;
                ldsm_x4(bf[2 * j][0], bf[2 * j][1], bf[2 * j + 1][0], bf[2 * j + 1][1],
                        stb + GCOMP * 4 + boff);
            }
#pragma unroll
            for (int mt = 0; mt < 2; mt++)
#pragma unroll
                for (int nt = 0; nt < 8; nt++)
                    mma_f16(acc[mt][nt], af[mt], bf[nt]);
        }
    }

    // ---- epilogue
#pragma unroll
    for (int mt = 0; mt < 2; mt++) {
#pragma unroll
        for (int e2 = 0; e2 < 2; e2++) {
            int r = row0 + wm * 32 + mt * 16 + gr + e2 * 8;
#pragma unroll
            for (int nt = 0; nt < 8; nt++) {
                int n = col0 + wn * 64 + nt * 8 + 2 * tig;
                float v0 = acc[mt][nt][e2 * 2 + 0];
                float v1 = acc[mt][nt][e2 * 2 + 1];
                if (MODE == 0) {
                    *(float2*)&C[(size_t)r * N + n] = make_float2(v0, v1);
                } else {
                    int b   = r >> 11;            // / SEQ
                    int tk  = r & (SEQ - 1);
                    int sec = n >> 10;
                    int c   = n & 1023;
                    int h   = c >> 6;
                    int d   = c & 63;
                    int bh_ = b * NHEAD + h;
                    if (sec == 2) {
                        // V: single fp16, transposed [B,H,D,T]
                        size_t i0 = ((size_t)bh_ * HDIM + d) * SEQ + tk;
                        g_vt[i0]       = __float2half_rn(v0);
                        g_vt[i0 + SEQ] = __float2half_rn(v1);
                    } else if (sec == 0) {
                        // Q: pre-scaled by 1/sqrt(D) (exact power of two)
                        size_t i2 = (((size_t)bh_ * SEQ + tk) * HDIM + d) >> 1;
                        ((uint32_t*)g_q)[i2] = packh(v0 * 0.125f, v1 * 0.125f);
                    } else {
                        // K
                        size_t i2 = (((size_t)bh_ * SEQ + tk) * HDIM + d) >> 1;
                        ((uint32_t*)g_k)[i2] = packh(v0, v1);
                    }
                }
            }
        }
    }
}

// ---------------------------------------------------------------------------
// Causal flash attention, single-pass fp16 mma.sync. Br=128, Bc=64, D=64.
// 256 threads = 8 warps; warp w owns q rows [16w, 16w+16).
// Q fragments from gmem (pre-scaled at QKV epilogue). K/V via ldmatrix.x4.
// 3-stage cp.async ring -> ONE __syncthreads per iter, load issued ahead of
// compute. P packed register-direct. LPT scheduling. grid: (SEQ/128, B*H)
// ---------------------------------------------------------------------------
#define AST 36                                   // smem row stride in u32
#define ATT_STG_U32 (2 * 64 * AST)               // Ks, Vt per stage
#define ATT_SMEM (3 * ATT_STG_U32 * 4)           // 55296 bytes

__global__ void __launch_bounds__(256, 2)
attn_h1()
{
    extern __shared__ uint32_t smu[];
    const uint32_t smb = (uint32_t)__cvta_generic_to_shared(smu);
    uint32_t* Stg = smu;                    // 3 stages of {Ks, Vt}

    const int tid  = threadIdx.x;
    const int lane = tid & 31;
    const int w    = tid >> 5;
    const int gr   = lane >> 2;
    const int tig  = lane & 3;
    const int m0   = w * 16;

    // ldmatrix lane mapping for B-operand pairs (K and V tiles)
    const int lrowB = ((lane >> 4) & 1) * 8 + (lane & 7);
    const int lcolB = ((lane >> 3) & 1) * 4;

    const int qb = gridDim.x - 1 - blockIdx.x;   // longest-processing-time first
    const int bh = blockIdx.y;
    const int b  = bh >> 4;
    const int h  = bh & 15;
    const int q0 = qb * 128;

    const size_t bhoff = (size_t)bh * SEQ * HDIM;
    const size_t vtoff = (size_t)bh * HDIM * SEQ;

    // K/V prefetch (cp.async, 3-stage ring)
    auto loadKV = [&](int s, int kt) {
        const int k0 = kt * 64;
        uint32_t* st = Stg + s * ATT_STG_U32;
        for (int i = tid; i < 64 * 8; i += 256) {
            int row = i >> 3, ch = i & 7;
            uint32_t* d = st + row * AST + ch * 4;
            size_t gk = bhoff + (size_t)(k0 + row) * HDIM + ch * 8;
            size_t gv = vtoff + (size_t)row * SEQ + k0 + ch * 8;
            cpasync16(d,            g_k  + gk);
            cpasync16(d + 64 * AST, g_vt + gv);
        }
    };

    const int ktmax = 2 * qb + 1;          // >= 1 always
    loadKV(0, 0); CP_COMMIT();
    loadKV(1, 1); CP_COMMIT();

    // ---- Q fragments straight from gmem (already scaled by 0.125)
    uint32_t qf[4][4];
    {
        const uint32_t* qg = (const uint32_t*)(g_q + bhoff + (size_t)q0 * HDIM);
        const int r0i = (m0 + gr) * 32;          // u32 row stride = HDIM/2
        const int r1i = (m0 + gr + 8) * 32;
#pragma unroll
        for (int dk = 0; dk < 4; dk++) {
            qf[dk][0] = qg[r0i + dk * 8 + tig];
            qf[dk][1] = qg[r1i + dk * 8 + tig];
            qf[dk][2] = qg[r0i + dk * 8 + tig + 4];
            qf[dk][3] = qg[r1i + dk * 8 + tig + 4];
        }
    }

    float o[8][4];
#pragma unroll
    for (int nt = 0; nt < 8; nt++)
#pragma unroll
        for (int e = 0; e < 4; e++) o[nt][e] = 0.f;
    float mrow[2] = {-1e30f, -1e30f};
    float lrow[2] = {0.f, 0.f};

    for (int kt = 0; kt <= ktmax; kt++) {
        const int s = kt % 3;
        if (kt < ktmax) { CP_WAIT1(); } else { CP_WAIT0(); }
        __syncthreads();                       // single barrier per iter
        if (kt + 2 <= ktmax) { loadKV((kt + 2) % 3, kt + 2); CP_COMMIT(); }

        const uint32_t ksb = smb + (uint32_t)s * ATT_STG_U32 * 4;
        const uint32_t vtb = ksb + 64 * AST * 4;
        const int k0 = kt * 64;

        // ---- S = Q K^T (single pass), K fragments via ldmatrix
        float sfr[8][4];
#pragma unroll
        for (int nt = 0; nt < 8; nt++)
#pragma unroll
            for (int e = 0; e < 4; e++) sfr[nt][e] = 0.f;

#pragma unroll
        for (int dk = 0; dk < 4; dk++) {
            uint32_t kf[8][2];
#pragma unroll
            for (int j = 0; j < 4; j++) {
                uint32_t koff = ((j * 16 + lrowB) * AST + dk * 8 + lcolB) * 4;
                ldsm_x4(kf[2 * j][0], kf[2 * j][1], kf[2 * j + 1][0], kf[2 * j + 1][1],
                        ksb + koff);
            }
#pragma unroll
            for (int nt = 0; nt < 8; nt++)
                mma_f16(sfr[nt], qf[dk], kf[nt]);
        }

        // ---- causal mask (only near the diagonal)
        if (k0 + 63 > q0 + m0) {
#pragma unroll
            for (int nt = 0; nt < 8; nt++)
#pragma unroll
                for (int e = 0; e < 4; e++) {
                    int rg = q0 + m0 + gr + (e >> 1) * 8;
                    int cg = k0 + nt * 8 + 2 * tig + (e & 1);
                    if (cg > rg) sfr[nt][e] = -1e30f;
                }
        }

        // ---- online softmax (thread rows: gr, gr+8); p kept in sfr
        float mx0 = -1e30f, mx1 = -1e30f;
#pragma unroll
        for (int nt = 0; nt < 8; nt++) {
            mx0 = fmaxf(mx0, fmaxf(sfr[nt][0], sfr[nt][1]));
            mx1 = fmaxf(mx1, fmaxf(sfr[nt][2], sfr[nt][3]));
        }
        mx0 = fmaxf(mx0, __shfl_xor_sync(0xffffffffu, mx0, 1));
        mx0 = fmaxf(mx0, __shfl_xor_sync(0xffffffffu, mx0, 2));
        mx1 = fmaxf(mx1, __shfl_xor_sync(0xffffffffu, mx1, 1));
        mx1 = fmaxf(mx1, __shfl_xor_sync(0xffffffffu, mx1, 2));

        float nm0 = fmaxf(mrow[0], mx0);
        float nm1 = fmaxf(mrow[1], mx1);
        float f0  = __expf(mrow[0] - nm0);
        float f1  = __expf(mrow[1] - nm1);

        float ps0 = 0.f, ps1 = 0.f;
#pragma unroll
        for (int nt = 0; nt < 8; nt++) {
            sfr[nt][0] = __expf(sfr[nt][0] - nm0);
            sfr[nt][1] = __expf(sfr[nt][1] - nm0);
            sfr[nt][2] = __expf(sfr[nt][2] - nm1);
            sfr[nt][3] = __expf(sfr[nt][3] - nm1);
            ps0 += sfr[nt][0] + sfr[nt][1];
            ps1 += sfr[nt][2] + sfr[nt][3];
        }
        ps0 += __shfl_xor_sync(0xffffffffu, ps0, 1);
        ps0 += __shfl_xor_sync(0xffffffffu, ps0, 2);
        ps1 += __shfl_xor_sync(0xffffffffu, ps1, 1);
        ps1 += __shfl_xor_sync(0xffffffffu, ps1, 2);

        lrow[0] = lrow[0] * f0 + ps0;
        lrow[1] = lrow[1] * f1 + ps1;
        mrow[0] = nm0;
        mrow[1] = nm1;
#pragma unroll
        for (int nt = 0; nt < 8; nt++) {
            o[nt][0] *= f0; o[nt][1] *= f0;
            o[nt][2] *= f1; o[nt][3] *= f1;
        }

        // ---- O += P V (single pass), P packed register-direct, V via ldmatrix
#pragma unroll
        for (int kk = 0; kk < 4; kk++) {
            uint32_t pf[4];
            pf[0] = packh(sfr[2 * kk    ][0], sfr[2 * kk    ][1]);
            pf[1] = packh(sfr[2 * kk    ][2], sfr[2 * kk    ][3]);
            pf[2] = packh(sfr[2 * kk + 1][0], sfr[2 * kk + 1][1]);
            pf[3] = packh(sfr[2 * kk + 1][2], sfr[2 * kk + 1][3]);
            uint32_t vf[8][2];
#pragma unroll
            for (int j = 0; j < 4; j++) {
                uint32_t voff = ((j * 16 + lrowB) * AST + kk * 8 + lcolB) * 4;
                ldsm_x4(vf[2 * j][0], vf[2 * j][1], vf[2 * j + 1][0], vf[2 * j + 1][1],
                        vtb + voff);
            }
#pragma unroll
            for (int nt = 0; nt < 8; nt++)
                mma_f16(o[nt], pf, vf[nt]);
        }
    }

    // ---- normalize and store to g_ao (single fp16, [B*T, C])
    float inv0 = 1.0f / lrow[0];
    float inv1 = 1.0f / lrow[1];
    int r0 = q0 + m0 + gr;
    uint32_t* ao = (uint32_t*)g_ao;
#pragma unroll
    for (int nt = 0; nt < 8; nt++) {
        size_t cu = (size_t)h * 32 + nt * 4 + tig;   // u32 col
        ao[(size_t)(b * SEQ + r0) * (EMBED / 2) + cu] =
            packh(o[nt][0] * inv0, o[nt][1] * inv0);
        ao[(size_t)(b * SEQ + r0 + 8) * (EMBED / 2) + cu] =
            packh(o[nt][2] * inv1, o[nt][3] * inv1);
    }
}

// ---------------------------------------------------------------------------
extern "C" void kernel_launch(void* const* d_in, const int* in_sizes, int n_in,
                              void* d_out, int out_size)
{
    const float* x      = (const float*)d_in[0];   // [4,2048,1024]
    const float* W_qkv  = (const float*)d_in[1];   // [3072,1024]
    const float* W_proj = (const float*)d_in[2];   // [1024,1024]
    float* out = (float*)d_out;                    // [4,2048,1024]

    __half *xp, *wq, *wp, *ao;
    cudaGetSymbolAddress((void**)&xp, g_x);
    cudaGetSymbolAddress((void**)&wq, g_wq);
    cudaGetSymbolAddress((void**)&wp, g_wp);
    cudaGetSymbolAddress((void**)&ao, g_ao);

    // 0) prep: everything to single fp16
    {
        int n1 = MROWS * EMBED / 4, n2 = 3 * EMBED * EMBED / 4, n3 = EMBED * EMBED / 4;
        cvt_f32h<<<(n1 + 255) / 256, 256>>>((const float4*)x, (uint2*)xp, n1);
        cvt_f32h<<<(n2 + 255) / 256, 256>>>((const float4*)W_qkv, (uint2*)wq, n2);
        cvt_f32h<<<(n3 + 255) / 256, 256>>>((const float4*)W_proj, (uint2*)wp, n3);
    }

    // 1) QKV projection (single-pass fp16) with scatter epilogue
    {
        cudaFuncSetAttribute((const void*)gemm_h1<1>,
                             cudaFuncAttributeMaxDynamicSharedMemorySize, GEMM_SMEM);
        dim3 grid(3 * EMBED / 128, MROWS / 128);
        gemm_h1<1><<<grid, 256, GEMM_SMEM>>>(xp, wq, nullptr, EMBED, 3 * EMBED);
    }

    // 2) causal flash attention -> g_ao (single fp16)
    {
        cudaFuncSetAttribute((const void*)attn_h1,
                             cudaFuncAttributeMaxDynamicSharedMemorySize, ATT_SMEM);
        dim3 grid(SEQ / 128, BATCH * NHEAD);
        attn_h1<<<grid, 256, ATT_SMEM>>>();
    }

    // 3) output projection (single-pass fp16) -> d_out (fp32)
    {
        cudaFuncSetAttribute((const void*)gemm_h1<0>,
                             cudaFuncAttributeMaxDynamicSharedMemorySize, GEMM_SMEM);
        dim3 grid(EMBED / 128, MROWS / 128);
        gemm_h1<0><<<grid, 256, GEMM_SMEM>>>(ao, wp, out, EMBED, EMBED);
    }
}

// round 16
// speedup vs baseline: 2.7489x; 1.0381x over previous
#include <cuda_runtime.h>
#include <cuda_fp16.h>
#include <cstdint>

// Problem constants
#define EMBED   1024
#define NHEAD   16
#define HDIM    64
#define BATCH   4
#define SEQ     2048
#define MROWS   (BATCH * SEQ)                 // 8192
#define QKVN    (BATCH * NHEAD * SEQ * HDIM)  // 8388608

// ---------------------------------------------------------------------------
// Persistent scratch (all single fp16)
// ---------------------------------------------------------------------------
__device__ __align__(16) __half g_x  [MROWS * EMBED];
__device__ __align__(16) __half g_wq [3 * EMBED * EMBED];
__device__ __align__(16) __half g_wp [EMBED * EMBED];
__device__ __align__(16) __half g_q  [QKVN];   // [B,H,T,D], pre-scaled by 0.125
__device__ __align__(16) __half g_k  [QKVN];   // [B,H,T,D]
__device__ __align__(16) __half g_vt [QKVN];   // [B,H,D,T] (transposed)
__device__ __align__(16) __half g_ao [MROWS * EMBED];   // [B*T, C]

// ---------------------------------------------------------------------------
// helpers
// ---------------------------------------------------------------------------
__device__ __forceinline__ void mma_f16(float* c, const uint32_t* a, const uint32_t* b) {
    asm volatile(
        "mma.sync.aligned.m16n8k16.row.col.f32.f16.f16.f32 "
        "{%0,%1,%2,%3}, {%4,%5,%6,%7}, {%8,%9}, {%0,%1,%2,%3};"
        : "+f"(c[0]), "+f"(c[1]), "+f"(c[2]), "+f"(c[3])
        : "r"(a[0]), "r"(a[1]), "r"(a[2]), "r"(a[3]), "r"(b[0]), "r"(b[1]));
}
__device__ __forceinline__ void ldsm_x4(uint32_t& r0, uint32_t& r1,
                                        uint32_t& r2, uint32_t& r3, uint32_t addr) {
    asm volatile("ldmatrix.sync.aligned.m8n8.x4.shared.b16 {%0,%1,%2,%3}, [%4];"
        : "=r"(r0), "=r"(r1), "=r"(r2), "=r"(r3) : "r"(addr));
}
__device__ __forceinline__ uint32_t packh(float x0, float x1) {
    __half2 h = __floats2half2_rn(x0, x1);
    return *(uint32_t*)&h;
}
__device__ __forceinline__ void cpasync16(void* s, const void* g) {
    uint32_t sa = (uint32_t)__cvta_generic_to_shared(s);
    asm volatile("cp.async.cg.shared.global [%0], [%1], 16;\n" :: "r"(sa), "l"(g));
}
#define CP_COMMIT() asm volatile("cp.async.commit_group;\n" ::: "memory")
#define CP_WAIT1()  asm volatile("cp.async.wait_group 1;\n"  ::: "memory")
#define CP_WAIT0()  asm volatile("cp.async.wait_group 0;\n"  ::: "memory")

// ---------------------------------------------------------------------------
// prep kernel: fp32 -> fp16
// ---------------------------------------------------------------------------
__global__ void cvt_f32h(const float4* __restrict__ src,
                         uint2* __restrict__ dst, int n4)
{
    int i = blockIdx.x * blockDim.x + threadIdx.x;
    if (i < n4) {
        float4 v = src[i];
        dst[i] = make_uint2(packh(v.x, v.y), packh(v.z, v.w));
    }
}

// ---------------------------------------------------------------------------
// single-pass fp16 GEMM:  C = A @ B^T.  A:[M,K] rm fp16, B:[N,K] rm fp16.
// Block 128x128, kTile 64 (fp16) -> 64 MMAs per barrier section, nk=16.
// 256 threads (8 warps, warp tile 32x64). 2-stage cp.async pipeline,
// fragments via ldmatrix.x4 (GST=36: 16B-aligned rows, conflict-free).
// MODE 0: fp32 store C.  MODE 1: QKV scatter epilogue (Q pre-scaled 0.125).
// ---------------------------------------------------------------------------
#define GST    36                          // smem row stride in u32 (32 data + 4 pad)
#define GCOMP  (128 * GST)                 // u32 per component per stage
#define GSTAGE (2 * GCOMP)                 // A, B
#define GEMM_SMEM (2 * GSTAGE * 4)         // 73728 bytes

template <int MODE>
__global__ void __launch_bounds__(256, 2)
gemm_h1(const __half* __restrict__ A, const __half* __restrict__ B,
        float* __restrict__ C, int K, int N)
{
    extern __shared__ uint32_t smu[];
    const uint32_t smb = (uint32_t)__cvta_generic_to_shared(smu);

    const int tid  = threadIdx.x;
    const int lane = tid & 31;
    const int w    = tid >> 5;
    const int gr   = lane >> 2;
    const int tig  = lane & 3;
    const int wm   = w & 3;              // 32-row quadrant
    const int wn   = w >> 2;             // 64-col half

    // ldmatrix lane mappings
    const int lrowA = (lane & 7) + ((lane >> 3) & 1) * 8;
    const int lcolA = (lane >> 4) * 4;
    const int lrowB = ((lane >> 4) & 1) * 8 + (lane & 7);
    const int lcolB = ((lane >> 3) & 1) * 4;

    const int row0 = blockIdx.y * 128;
    const int col0 = blockIdx.x * 128;

    float acc[2][8][4];
#pragma unroll
    for (int i = 0; i < 2; i++)
#pragma unroll
        for (int j = 0; j < 8; j++)
#pragma unroll
            for (int e = 0; e < 4; e++) acc[i][j][e] = 0.f;

    // stage loader: per component 128 rows x 64 fp16 (8 x 16B chunks per row)
    auto loadTile = [&](int s, int kt) {
        uint32_t* st = smu + (size_t)s * GSTAGE;
#pragma unroll
        for (int p = 0; p < 4; p++) {
            int c   = tid + 256 * p;         // 0..1023
            int row = c >> 3;
            int ch  = c & 7;
            uint32_t* d0 = st + row * GST + ch * 4;
            size_t ga = (size_t)(row0 + row) * K + kt + ch * 8;
            size_t gb = (size_t)(col0 + row) * K + kt + ch * 8;
            cpasync16(d0,         A + ga);
            cpasync16(d0 + GCOMP, B + gb);
        }
    };

    const int nk = K / 64;
    loadTile(0, 0);  CP_COMMIT();
    loadTile(1, 64); CP_COMMIT();

    for (int t = 0; t < nk; t++) {
        const int s = t & 1;
        if (t >= nk - 2) { CP_WAIT0(); } else { CP_WAIT1(); }
        __syncthreads();

        const uint32_t stb = smb + (uint32_t)s * GSTAGE * 4;

#pragma unroll
        for (int ks = 0; ks < 4; ks++) {
            const int base = ks * 8;
            uint32_t af[2][4];
#pragma unroll
            for (int mt = 0; mt < 2; mt++) {
                uint32_t aoff = ((wm * 32 + mt * 16 + lrowA) * GST + base + lcolA) * 4;
                ldsm_x4(af[mt][0], af[mt][1], af[mt][2], af[mt][3], stb + aoff);
            }
            uint32_t bf[8][2];
#pragma unroll
            for (int j = 0; j < 4; j++) {
                uint32_t boff = ((wn * 64 + j * 16 + lrowB) * GST + base + lcolB) * 4;
                ldsm_x4(bf[2 * j][0], bf[2 * j][1], bf[2 * j + 1][0], bf[2 * j + 1][1],
                        stb + GCOMP * 4 + boff);
            }
#pragma unroll
            for (int mt = 0; mt < 2; mt++)
#pragma unroll
                for (int nt = 0; nt < 8; nt++)
                    mma_f16(acc[mt][nt], af[mt], bf[nt]);
        }
        __syncthreads();
        if (t + 2 < nk) { loadTile(s, (t + 2) * 64); CP_COMMIT(); }
    }

    // ---- epilogue
#pragma unroll
    for (int mt = 0; mt < 2; mt++) {
#pragma unroll
        for (int e2 = 0; e2 < 2; e2++) {
            int r = row0 + wm * 32 + mt * 16 + gr + e2 * 8;
#pragma unroll
            for (int nt = 0; nt < 8; nt++) {
                int n = col0 + wn * 64 + nt * 8 + 2 * tig;
                float v0 = acc[mt][nt][e2 * 2 + 0];
                float v1 = acc[mt][nt][e2 * 2 + 1];
                if (MODE == 0) {
                    *(float2*)&C[(size_t)r * N + n] = make_float2(v0, v1);
                } else {
                    int b   = r >> 11;            // / SEQ
                    int tk  = r & (SEQ - 1);
                    int sec = n >> 10;
                    int c   = n & 1023;
                    int h   = c >> 6;
                    int d   = c & 63;
                    int bh_ = b * NHEAD + h;
                    if (sec == 2) {
                        // V: single fp16, transposed [B,H,D,T]
                        size_t i0 = ((size_t)bh_ * HDIM + d) * SEQ + tk;
                        g_vt[i0]       = __float2half_rn(v0);
                        g_vt[i0 + SEQ] = __float2half_rn(v1);
                    } else if (sec == 0) {
                        // Q: pre-scaled by 1/sqrt(D) (exact power of two)
                        size_t i2 = (((size_t)bh_ * SEQ + tk) * HDIM + d) >> 1;
                        ((uint32_t*)g_q)[i2] = packh(v0 * 0.125f, v1 * 0.125f);
                    } else {
                        // K
                        size_t i2 = (((size_t)bh_ * SEQ + tk) * HDIM + d) >> 1;
                        ((uint32_t*)g_k)[i2] = packh(v0, v1);
                    }
                }
            }
        }
    }
}

// ---------------------------------------------------------------------------
// Causal flash attention, single-pass fp16 mma.sync. Br=128, Bc=64, D=64.
// 256 threads = 8 warps; warp w owns q rows [16w, 16w+16).
// Q fragments from gmem (pre-scaled at QKV epilogue). K/V via ldmatrix.x4.
// 3-stage cp.async ring -> ONE __syncthreads per iter, load issued ahead of
// compute. P packed register-direct. LPT scheduling. grid: (SEQ/128, B*H)
// ---------------------------------------------------------------------------
#define AST 36                                   // smem row stride in u32
#define ATT_STG_U32 (2 * 64 * AST)               // Ks, Vt per stage
#define ATT_SMEM (3 * ATT_STG_U32 * 4)           // 55296 bytes

__global__ void __launch_bounds__(256, 2)
attn_h1()
{
    extern __shared__ uint32_t smu[];
    const uint32_t smb = (uint32_t)__cvta_generic_to_shared(smu);
    uint32_t* Stg = smu;                    // 3 stages of {Ks, Vt}

    const int tid  = threadIdx.x;
    const int lane = tid & 31;
    const int w    = tid >> 5;
    const int gr   = lane >> 2;
    const int tig  = lane & 3;
    const int m0   = w * 16;

    // ldmatrix lane mapping for B-operand pairs (K and V tiles)
    const int lrowB = ((lane >> 4) & 1) * 8 + (lane & 7);
    const int lcolB = ((lane >> 3) & 1) * 4;

    const int qb = gridDim.x - 1 - blockIdx.x;   // longest-processing-time first
    const int bh = blockIdx.y;
    const int b  = bh >> 4;
    const int h  = bh & 15;
    const int q0 = qb * 128;

    const size_t bhoff = (size_t)bh * SEQ * HDIM;
    const size_t vtoff = (size_t)bh * HDIM * SEQ;

    // K/V prefetch (cp.async, 3-stage ring)
    auto loadKV = [&](int s, int kt) {
        const int k0 = kt * 64;
        uint32_t* st = Stg + s * ATT_STG_U32;
        for (int i = tid; i < 64 * 8; i += 256) {
            int row = i >> 3, ch = i & 7;
            uint32_t* d = st + row * AST + ch * 4;
            size_t gk = bhoff + (size_t)(k0 + row) * HDIM + ch * 8;
            size_t gv = vtoff + (size_t)row * SEQ + k0 + ch * 8;
            cpasync16(d,            g_k  + gk);
            cpasync16(d + 64 * AST, g_vt + gv);
        }
    };

    const int ktmax = 2 * qb + 1;          // >= 1 always
    loadKV(0, 0); CP_COMMIT();
    loadKV(1, 1); CP_COMMIT();

    // ---- Q fragments straight from gmem (already scaled by 0.125)
    uint32_t qf[4][4];
    {
        const uint32_t* qg = (const uint32_t*)(g_q + bhoff + (size_t)q0 * HDIM);
        const int r0i = (m0 + gr) * 32;          // u32 row stride = HDIM/2
        const int r1i = (m0 + gr + 8) * 32;
#pragma unroll
        for (int dk = 0; dk < 4; dk++) {
            qf[dk][0] = qg[r0i + dk * 8 + tig];
            qf[dk][1] = qg[r1i + dk * 8 + tig];
            qf[dk][2] = qg[r0i + dk * 8 + tig + 4];
            qf[dk][3] = qg[r1i + dk * 8 + tig + 4];
        }
    }

    float o[8][4];
#pragma unroll
    for (int nt = 0; nt < 8; nt++)
#pragma unroll
        for (int e = 0; e < 4; e++) o[nt][e] = 0.f;
    float mrow[2] = {-1e30f, -1e30f};
    float lrow[2] = {0.f, 0.f};

    for (int kt = 0; kt <= ktmax; kt++) {
        const int s = kt % 3;
        if (kt < ktmax) { CP_WAIT1(); } else { CP_WAIT0(); }
        __syncthreads();                       // single barrier per iter
        if (kt + 2 <= ktmax) { loadKV((kt + 2) % 3, kt + 2); CP_COMMIT(); }

        const uint32_t ksb = smb + (uint32_t)s * ATT_STG_U32 * 4;
        const uint32_t vtb = ksb + 64 * AST * 4;
        const int k0 = kt * 64;

        // ---- S = Q K^T (single pass), K fragments via ldmatrix
        float sfr[8][4];
#pragma unroll
        for (int nt = 0; nt < 8; nt++)
#pragma unroll
            for (int e = 0; e < 4; e++) sfr[nt][e] = 0.f;

#pragma unroll
        for (int dk = 0; dk < 4; dk++) {
            uint32_t kf[8][2];
#pragma unroll
            for (int j = 0; j < 4; j++) {
                uint32_t koff = ((j * 16 + lrowB) * AST + dk * 8 + lcolB) * 4;
                ldsm_x4(kf[2 * j][0], kf[2 * j][1], kf[2 * j + 1][0], kf[2 * j + 1][1],
                        ksb + koff);
            }
#pragma unroll
            for (int nt = 0; nt < 8; nt++)
                mma_f16(sfr[nt], qf[dk], kf[nt]);
        }

        // ---- causal mask (only near the diagonal)
        if (k0 + 63 > q0 + m0) {
#pragma unroll
            for (int nt = 0; nt < 8; nt++)
#pragma unroll
                for (int e = 0; e < 4; e++) {
                    int rg = q0 + m0 + gr + (e >> 1) * 8;
                    int cg = k0 + nt * 8 + 2 * tig + (e & 1);
                    if (cg > rg) sfr[nt][e] = -1e30f;
                }
        }

        // ---- online softmax (thread rows: gr, gr+8); p kept in sfr
        float mx0 = -1e30f, mx1 = -1e30f;
#pragma unroll
        for (int nt = 0; nt < 8; nt++) {
            mx0 = fmaxf(mx0, fmaxf(sfr[nt][0], sfr[nt][1]));
            mx1 = fmaxf(mx1, fmaxf(sfr[nt][2], sfr[nt][3]));
        }
        mx0 = fmaxf(mx0, __shfl_xor_sync(0xffffffffu, mx0, 1));
        mx0 = fmaxf(mx0, __shfl_xor_sync(0xffffffffu, mx0, 2));
        mx1 = fmaxf(mx1, __shfl_xor_sync(0xffffffffu, mx1, 1));
        mx1 = fmaxf(mx1, __shfl_xor_sync(0xffffffffu, mx1, 2));

        float nm0 = fmaxf(mrow[0], mx0);
        float nm1 = fmaxf(mrow[1], mx1);
        float f0  = __expf(mrow[0] - nm0);
        float f1  = __expf(mrow[1] - nm1);

        float ps0 = 0.f, ps1 = 0.f;
#pragma unroll
        for (int nt = 0; nt < 8; nt++) {
            sfr[nt][0] = __expf(sfr[nt][0] - nm0);
            sfr[nt][1] = __expf(sfr[nt][1] - nm0);
            sfr[nt][2] = __expf(sfr[nt][2] - nm1);
            sfr[nt][3] = __expf(sfr[nt][3] - nm1);
            ps0 += sfr[nt][0] + sfr[nt][1];
            ps1 += sfr[nt][2] + sfr[nt][3];
        }
        ps0 += __shfl_xor_sync(0xffffffffu, ps0, 1);
        ps0 += __shfl_xor_sync(0xffffffffu, ps0, 2);
        ps1 += __shfl_xor_sync(0xffffffffu, ps1, 1);
        ps1 += __shfl_xor_sync(0xffffffffu, ps1, 2);

        lrow[0] = lrow[0] * f0 + ps0;
        lrow[1] = lrow[1] * f1 + ps1;
        mrow[0] = nm0;
        mrow[1] = nm1;
#pragma unroll
        for (int nt = 0; nt < 8; nt++) {
            o[nt][0] *= f0; o[nt][1] *= f0;
            o[nt][2] *= f1; o[nt][3] *= f1;
        }

        // ---- O += P V (single pass), P packed register-direct, V via ldmatrix
#pragma unroll
        for (int kk = 0; kk < 4; kk++) {
            uint32_t pf[4];
            pf[0] = packh(sfr[2 * kk    ][0], sfr[2 * kk    ][1]);
            pf[1] = packh(sfr[2 * kk    ][2], sfr[2 * kk    ][3]);
            pf[2] = packh(sfr[2 * kk + 1][0], sfr[2 * kk + 1][1]);
            pf[3] = packh(sfr[2 * kk + 1][2], sfr[2 * kk + 1][3]);
            uint32_t vf[8][2];
#pragma unroll
            for (int j = 0; j < 4; j++) {
                uint32_t voff = ((j * 16 + lrowB) * AST + kk * 8 + lcolB) * 4;
                ldsm_x4(vf[2 * j][0], vf[2 * j][1], vf[2 * j + 1][0], vf[2 * j + 1][1],
                        vtb + voff);
            }
#pragma unroll
            for (int nt = 0; nt < 8; nt++)
                mma_f16(o[nt], pf, vf[nt]);
        }
    }

    // ---- normalize and store to g_ao (single fp16, [B*T, C])
    float inv0 = 1.0f / lrow[0];
    float inv1 = 1.0f / lrow[1];
    int r0 = q0 + m0 + gr;
    uint32_t* ao = (uint32_t*)g_ao;
#pragma unroll
    for (int nt = 0; nt < 8; nt++) {
        size_t cu = (size_t)h * 32 + nt * 4 + tig;   // u32 col
        ao[(size_t)(b * SEQ + r0) * (EMBED / 2) + cu] =
            packh(o[nt][0] * inv0, o[nt][1] * inv0);
        ao[(size_t)(b * SEQ + r0 + 8) * (EMBED / 2) + cu] =
            packh(o[nt][2] * inv1, o[nt][3] * inv1);
    }
}

// ---------------------------------------------------------------------------
extern "C" void kernel_launch(void* const* d_in, const int* in_sizes, int n_in,
                              void* d_out, int out_size)
{
    const float* x      = (const float*)d_in[0];   // [4,2048,1024]
    const float* W_qkv  = (const float*)d_in[1];   // [3072,1024]
    const float* W_proj = (const float*)d_in[2];   // [1024,1024]
    float* out = (float*)d_out;                    // [4,2048,1024]

    __half *xp, *wq, *wp, *ao;
    cudaGetSymbolAddress((void**)&xp, g_x);
    cudaGetSymbolAddress((void**)&wq, g_wq);
    cudaGetSymbolAddress((void**)&wp, g_wp);
    cudaGetSymbolAddress((void**)&ao, g_ao);

    // 0) prep: everything to single fp16
    {
        int n1 = MROWS * EMBED / 4, n2 = 3 * EMBED * EMBED / 4, n3 = EMBED * EMBED / 4;
        cvt_f32h<<<(n1 + 255) / 256, 256>>>((const float4*)x, (uint2*)xp, n1);
        cvt_f32h<<<(n2 + 255) / 256, 256>>>((const float4*)W_qkv, (uint2*)wq, n2);
        cvt_f32h<<<(n3 + 255) / 256, 256>>>((const float4*)W_proj, (uint2*)wp, n3);
    }

    // 1) QKV projection (single-pass fp16, kTile=64) with scatter epilogue
    {
        cudaFuncSetAttribute((const void*)gemm_h1<1>,
                             cudaFuncAttributeMaxDynamicSharedMemorySize, GEMM_SMEM);
        dim3 grid(3 * EMBED / 128, MROWS / 128);
        gemm_h1<1><<<grid, 256, GEMM_SMEM>>>(xp, wq, nullptr, EMBED, 3 * EMBED);
    }

    // 2) causal flash attention -> g_ao (single fp16)
    {
        cudaFuncSetAttribute((const void*)attn_h1,
                             cudaFuncAttributeMaxDynamicSharedMemorySize, ATT_SMEM);
        dim3 grid(SEQ / 128, BATCH * NHEAD);
        attn_h1<<<grid, 256, ATT_SMEM>>>();
    }

    // 3) output projection (single-pass fp16, kTile=64) -> d_out (fp32)
    {
        cudaFuncSetAttribute((const void*)gemm_h1<0>,
                             cudaFuncAttributeMaxDynamicSharedMemorySize, GEMM_SMEM);
        dim3 grid(EMBED / 128, MROWS / 128);
        gemm_h1<0><<<grid, 256, GEMM_SMEM>>>(ao, wp, out, EMBED, EMBED);
    }
}